// round 1
// baseline (speedup 1.0000x reference)
#include <cuda_runtime.h>
#include <math.h>

// Problem constants
#define B_  2
#define S_  2048
#define D_  1024
#define H_  16
#define DK_ 64

// Scratch (device globals: no allocations allowed)
__device__ float g_Q[B_*S_*D_];
__device__ float g_K[B_*S_*D_];
__device__ float g_V[B_*S_*D_];
__device__ float g_ctx[B_*S_*D_];

// ---------------------------------------------------------------------------
// GEMM (NT + bias): C[M,N] = A[M,K] @ W[N,K]^T + bias[N]
// 128x128x16 tiles, 256 threads, 8x8 per-thread register blocking.
// ---------------------------------------------------------------------------
__global__ __launch_bounds__(256) void gemm_bias_nt(
    const float* __restrict__ A, const float* __restrict__ W,
    const float* __restrict__ bias, float* __restrict__ C,
    int M, int N, int K)
{
    const int BM = 128, BN = 128, BK = 16;
    __shared__ float As[BK][BM + 4];
    __shared__ float Ws[BK][BN + 4];

    const int tid = threadIdx.x;
    const int ty = tid >> 4;      // 0..15
    const int tx = tid & 15;      // 0..15
    const int bm = blockIdx.y * BM;
    const int bn = blockIdx.x * BN;

    float acc[8][8];
    #pragma unroll
    for (int i = 0; i < 8; i++)
        #pragma unroll
        for (int j = 0; j < 8; j++) acc[i][j] = 0.0f;

    for (int k0 = 0; k0 < K; k0 += BK) {
        // Load A and W tiles (transposed into [BK][BM]) with float4s.
        #pragma unroll
        for (int it = 0; it < 2; ++it) {
            int idx = tid + it * 256;          // 0..511
            int row = idx >> 2;                // 0..127
            int kv  = (idx & 3) * 4;           // 0,4,8,12
            float4 av = *(const float4*)&A[(size_t)(bm + row) * K + k0 + kv];
            As[kv + 0][row] = av.x; As[kv + 1][row] = av.y;
            As[kv + 2][row] = av.z; As[kv + 3][row] = av.w;
            float4 wv = *(const float4*)&W[(size_t)(bn + row) * K + k0 + kv];
            Ws[kv + 0][row] = wv.x; Ws[kv + 1][row] = wv.y;
            Ws[kv + 2][row] = wv.z; Ws[kv + 3][row] = wv.w;
        }
        __syncthreads();

        #pragma unroll
        for (int kk = 0; kk < BK; kk++) {
            float4 a0 = *(const float4*)&As[kk][ty * 8];
            float4 a1 = *(const float4*)&As[kk][ty * 8 + 4];
            float4 b0 = *(const float4*)&Ws[kk][tx * 8];
            float4 b1 = *(const float4*)&Ws[kk][tx * 8 + 4];
            float a[8] = {a0.x, a0.y, a0.z, a0.w, a1.x, a1.y, a1.z, a1.w};
            float b[8] = {b0.x, b0.y, b0.z, b0.w, b1.x, b1.y, b1.z, b1.w};
            #pragma unroll
            for (int i = 0; i < 8; i++)
                #pragma unroll
                for (int j = 0; j < 8; j++)
                    acc[i][j] = fmaf(a[i], b[j], acc[i][j]);
        }
        __syncthreads();
    }

    #pragma unroll
    for (int i = 0; i < 8; i++) {
        int m = bm + ty * 8 + i;
        #pragma unroll
        for (int j = 0; j < 8; j += 4) {
            int n = bn + tx * 8 + j;
            float4 v;
            v.x = acc[i][j + 0] + bias[n + 0];
            v.y = acc[i][j + 1] + bias[n + 1];
            v.z = acc[i][j + 2] + bias[n + 2];
            v.w = acc[i][j + 3] + bias[n + 3];
            *(float4*)&C[(size_t)m * N + n] = v;
        }
    }
}

// ---------------------------------------------------------------------------
// Flash-style attention: per (q-tile of 64, head, batch) block.
// Online softmax over 64-key tiles; K held transposed in SMEM; P@V from SMEM.
// ---------------------------------------------------------------------------
__global__ __launch_bounds__(256) void attn_kernel(
    const float* __restrict__ Q, const float* __restrict__ K,
    const float* __restrict__ V, const int* __restrict__ mask,
    float* __restrict__ ctx)
{
    extern __shared__ float sm[];
    float* Qs  = sm;                 // [64][68]  q-major, d inner
    float* KsT = sm + 64 * 68;       // [64][68]  d-major, k inner (transposed)
    float* Vs  = sm + 2 * 64 * 68;   // [64][68]  k-major, d inner
    float* Ps  = sm + 3 * 64 * 68;   // [64][68]  q-major, k inner
    __shared__ int ms[64];

    const int tid = threadIdx.x;
    const int ty = tid >> 4;   // 0..15 -> q block of 4
    const int tx = tid & 15;   // 0..15 -> k (phase1) / d (phase2) block of 4
    const int b = blockIdx.z, h = blockIdx.y;
    const int q0 = blockIdx.x * 64;
    const float scale = 0.125f;  // 1/sqrt(64)

    // Load Q tile (pre-scaled)
    #pragma unroll
    for (int it = 0; it < 4; ++it) {
        int idx = tid + it * 256;      // 0..1023
        int r = idx >> 4;              // 0..63
        int c4 = (idx & 15) * 4;       // 0..60
        float4 v = *(const float4*)&Q[((size_t)(b * S_ + q0 + r)) * D_ + h * DK_ + c4];
        Qs[r * 68 + c4 + 0] = v.x * scale;
        Qs[r * 68 + c4 + 1] = v.y * scale;
        Qs[r * 68 + c4 + 2] = v.z * scale;
        Qs[r * 68 + c4 + 3] = v.w * scale;
    }

    float m_i[4], l_i[4], acc[4][4];
    #pragma unroll
    for (int i = 0; i < 4; i++) {
        m_i[i] = -1e30f; l_i[i] = 0.0f;
        #pragma unroll
        for (int j = 0; j < 4; j++) acc[i][j] = 0.0f;
    }

    for (int k0 = 0; k0 < S_; k0 += 64) {
        __syncthreads();  // protect KsT/Vs from previous iteration's readers
        #pragma unroll
        for (int it = 0; it < 4; ++it) {
            int idx = tid + it * 256;
            int r = idx >> 4;
            int c4 = (idx & 15) * 4;
            float4 kv = *(const float4*)&K[((size_t)(b * S_ + k0 + r)) * D_ + h * DK_ + c4];
            KsT[(c4 + 0) * 68 + r] = kv.x;
            KsT[(c4 + 1) * 68 + r] = kv.y;
            KsT[(c4 + 2) * 68 + r] = kv.z;
            KsT[(c4 + 3) * 68 + r] = kv.w;
            float4 vv = *(const float4*)&V[((size_t)(b * S_ + k0 + r)) * D_ + h * DK_ + c4];
            Vs[r * 68 + c4 + 0] = vv.x;
            Vs[r * 68 + c4 + 1] = vv.y;
            Vs[r * 68 + c4 + 2] = vv.z;
            Vs[r * 68 + c4 + 3] = vv.w;
        }
        if (tid < 64) ms[tid] = mask[b * S_ + k0 + tid];
        __syncthreads();

        // Phase 1: S = Qs @ K^T  (each thread 4q x 4k)
        float s[4][4];
        #pragma unroll
        for (int i = 0; i < 4; i++)
            #pragma unroll
            for (int j = 0; j < 4; j++) s[i][j] = 0.0f;

        #pragma unroll 4
        for (int d = 0; d < 64; ++d) {
            float4 bk = *(const float4*)&KsT[d * 68 + tx * 4];
            float bj[4] = {bk.x, bk.y, bk.z, bk.w};
            #pragma unroll
            for (int i = 0; i < 4; i++) {
                float aq = Qs[(ty * 4 + i) * 68 + d];
                #pragma unroll
                for (int j = 0; j < 4; j++)
                    s[i][j] = fmaf(aq, bj[j], s[i][j]);
            }
        }

        // Mask
        #pragma unroll
        for (int j = 0; j < 4; j++) {
            if (ms[tx * 4 + j] == 0) {
                #pragma unroll
                for (int i = 0; i < 4; i++) s[i][j] = -1e30f;
            }
        }

        // Online softmax (per-row reductions over 16 lanes sharing ty)
        float p[4][4];
        #pragma unroll
        for (int i = 0; i < 4; i++) {
            float rm = fmaxf(fmaxf(s[i][0], s[i][1]), fmaxf(s[i][2], s[i][3]));
            #pragma unroll
            for (int off = 1; off < 16; off <<= 1)
                rm = fmaxf(rm, __shfl_xor_sync(0xffffffffu, rm, off));
            float mnew = fmaxf(m_i[i], rm);
            float c = __expf(m_i[i] - mnew);
            m_i[i] = mnew;
            float rs = 0.0f;
            #pragma unroll
            for (int j = 0; j < 4; j++) {
                p[i][j] = __expf(s[i][j] - mnew);
                rs += p[i][j];
            }
            #pragma unroll
            for (int off = 1; off < 16; off <<= 1)
                rs += __shfl_xor_sync(0xffffffffu, rs, off);
            l_i[i] = l_i[i] * c + rs;
            #pragma unroll
            for (int j = 0; j < 4; j++) acc[i][j] *= c;
        }

        // Stage P
        #pragma unroll
        for (int i = 0; i < 4; i++)
            #pragma unroll
            for (int j = 0; j < 4; j++)
                Ps[(ty * 4 + i) * 68 + tx * 4 + j] = p[i][j];
        __syncthreads();

        // Phase 2: O += P @ V  (each thread 4q x 4d)
        #pragma unroll 4
        for (int k = 0; k < 64; ++k) {
            float4 vv = *(const float4*)&Vs[k * 68 + tx * 4];
            float bv[4] = {vv.x, vv.y, vv.z, vv.w};
            #pragma unroll
            for (int i = 0; i < 4; i++) {
                float ap = Ps[(ty * 4 + i) * 68 + k];
                #pragma unroll
                for (int j = 0; j < 4; j++)
                    acc[i][j] = fmaf(ap, bv[j], acc[i][j]);
            }
        }
    }

    // Epilogue: normalize and write context in [B,S,D] layout
    #pragma unroll
    for (int i = 0; i < 4; i++) {
        float inv = 1.0f / l_i[i];
        float4 v;
        v.x = acc[i][0] * inv; v.y = acc[i][1] * inv;
        v.z = acc[i][2] * inv; v.w = acc[i][3] * inv;
        *(float4*)&ctx[((size_t)(b * S_ + q0 + ty * 4 + i)) * D_ + h * DK_ + tx * 4] = v;
    }
}

// ---------------------------------------------------------------------------
extern "C" void kernel_launch(void* const* d_in, const int* in_sizes, int n_in,
                              void* d_out, int out_size)
{
    (void)in_sizes; (void)n_in; (void)out_size;
    const float* query = (const float*)d_in[0];
    const float* key   = (const float*)d_in[1];
    const float* value = (const float*)d_in[2];
    const int*   mask  = (const int*)d_in[3];
    const float* Wq = (const float*)d_in[4];
    const float* bq = (const float*)d_in[5];
    const float* Wk = (const float*)d_in[6];
    const float* bk = (const float*)d_in[7];
    const float* Wv = (const float*)d_in[8];
    const float* bv = (const float*)d_in[9];
    const float* Wo = (const float*)d_in[10];
    const float* bo = (const float*)d_in[11];
    float* out = (float*)d_out;

    float *Qb, *Kb, *Vb, *Cb;
    cudaGetSymbolAddress((void**)&Qb, g_Q);
    cudaGetSymbolAddress((void**)&Kb, g_K);
    cudaGetSymbolAddress((void**)&Vb, g_V);
    cudaGetSymbolAddress((void**)&Cb, g_ctx);

    const int M = B_ * S_;   // 4096
    dim3 gthr(256);
    dim3 ggrid(D_ / 128, M / 128);   // (8, 32)

    gemm_bias_nt<<<ggrid, gthr>>>(query, Wq, bq, Qb, M, D_, D_);
    gemm_bias_nt<<<ggrid, gthr>>>(key,   Wk, bk, Kb, M, D_, D_);
    gemm_bias_nt<<<ggrid, gthr>>>(value, Wv, bv, Vb, M, D_, D_);

    static const size_t attn_smem = 4 * 64 * 68 * sizeof(float);  // 69632 B
    cudaFuncSetAttribute(attn_kernel, cudaFuncAttributeMaxDynamicSharedMemorySize,
                         (int)attn_smem);
    dim3 agrid(S_ / 64, H_, B_);     // (32, 16, 2)
    attn_kernel<<<agrid, gthr, attn_smem>>>(Qb, Kb, Vb, mask, Cb);

    gemm_bias_nt<<<ggrid, gthr>>>(Cb, Wo, bo, out, M, D_, D_);
}

// round 3
// speedup vs baseline: 1.2370x; 1.2370x over previous
#include <cuda_runtime.h>
#include <cuda_bf16.h>
#include <math.h>
#include <stdint.h>

// Problem constants
#define B_  2
#define S_  2048
#define D_  1024
#define H_  16
#define DK_ 64

// GEMM tiling
#define BM 128
#define BN 256
#define BK 32
#define KDIM 1024
#define CHUNKS 96           // 3 * KDIM / BK  (hi*hi, hi*lo, lo*hi segments)
#define ASZ (BM * 40 * 2)   // bf16 tile 128 x 32, padded stride 40
#define BSZ (BN * 40 * 2)

// Scratch (device globals: no allocations allowed)
__device__ float g_Q[B_*S_*D_];
__device__ float g_K[B_*S_*D_];
__device__ float g_V[B_*S_*D_];
__device__ float g_ctx[B_*S_*D_];
__device__ __nv_bfloat16 g_act_hi[B_*S_*D_];
__device__ __nv_bfloat16 g_act_lo[B_*S_*D_];
__device__ __nv_bfloat16 g_w_hi[D_*D_];
__device__ __nv_bfloat16 g_w_lo[D_*D_];

// ===========================================================================
// Helpers
// ===========================================================================
__device__ __forceinline__ uint32_t smem_u32(const void* p) {
    uint32_t a;
    asm("{ .reg .u64 t; cvta.to.shared.u64 t, %1; cvt.u32.u64 %0, t; }"
        : "=r"(a) : "l"(p));
    return a;
}

__device__ __forceinline__ void cp16(uint32_t dst, const void* src) {
    asm volatile("cp.async.cg.shared.global [%0], [%1], 16;"
                 :: "r"(dst), "l"(src));
}

__device__ __forceinline__ void ldmx4(uint32_t& r0, uint32_t& r1,
                                      uint32_t& r2, uint32_t& r3, uint32_t addr) {
    asm volatile("ldmatrix.sync.aligned.m8n8.x4.shared.b16 {%0,%1,%2,%3}, [%4];"
                 : "=r"(r0), "=r"(r1), "=r"(r2), "=r"(r3) : "r"(addr));
}

__device__ __forceinline__ void mma16816(float* c, const uint32_t* a,
                                         uint32_t b0, uint32_t b1) {
    asm volatile(
        "mma.sync.aligned.m16n8k16.row.col.f32.bf16.bf16.f32 "
        "{%0,%1,%2,%3}, {%4,%5,%6,%7}, {%8,%9}, {%0,%1,%2,%3};"
        : "+f"(c[0]), "+f"(c[1]), "+f"(c[2]), "+f"(c[3])
        : "r"(a[0]), "r"(a[1]), "r"(a[2]), "r"(a[3]), "r"(b0), "r"(b1));
}

__device__ __forceinline__ uint32_t pack2(unsigned short a, unsigned short b) {
    return (uint32_t)a | ((uint32_t)b << 16);
}

// ===========================================================================
// Split fp32 -> (hi, lo) bf16 pair
// ===========================================================================
__global__ __launch_bounds__(256) void split_hl(
    const float* __restrict__ x, __nv_bfloat16* __restrict__ hi,
    __nv_bfloat16* __restrict__ lo, int n4)
{
    int i = blockIdx.x * blockDim.x + threadIdx.x;
    if (i >= n4) return;
    float4 v = ((const float4*)x)[i];
    float f[4] = {v.x, v.y, v.z, v.w};
    unsigned short h[4], l[4];
    #pragma unroll
    for (int j = 0; j < 4; j++) {
        __nv_bfloat16 bh = __float2bfloat16(f[j]);
        float r = f[j] - __bfloat162float(bh);
        __nv_bfloat16 bl = __float2bfloat16(r);
        h[j] = __bfloat16_as_ushort(bh);
        l[j] = __bfloat16_as_ushort(bl);
    }
    ((uint2*)hi)[i] = make_uint2(pack2(h[0], h[1]), pack2(h[2], h[3]));
    ((uint2*)lo)[i] = make_uint2(pack2(l[0], l[1]), pack2(l[2], l[3]));
}

// ===========================================================================
// Tensor-core GEMM (NT + bias) via mma.sync bf16, hi/lo concat-K (K'=3072).
// C[4096,1024] = A[4096,1024] @ W[1024,1024]^T + bias
// 128x256 tile, 512 threads (16 warps, warp tile 32x64), cp.async dbl-buffer.
// ===========================================================================
__global__ __launch_bounds__(512) void gemm_mma(
    const __nv_bfloat16* __restrict__ aHi, const __nv_bfloat16* __restrict__ aLo,
    const __nv_bfloat16* __restrict__ bHi, const __nv_bfloat16* __restrict__ bLo,
    const float* __restrict__ bias, float* __restrict__ C)
{
    extern __shared__ char dynsm[];
    const uint32_t smbase = smem_u32(dynsm);
    const int tid = threadIdx.x;
    const int l = tid & 31;
    const int wid = tid >> 5;
    const int wm = (wid & 3) * 32;
    const int wn = (wid >> 2) * 64;
    const int bm = blockIdx.y * BM;
    const int bn = blockIdx.x * BN;

    // cp.async mapping (per thread): 1 A op + 2 B ops, 16B each
    const int arow = tid >> 2;
    const int as4 = (tid & 3) * 8;

    float acc[2][8][4];
    #pragma unroll
    for (int mi = 0; mi < 2; mi++)
        #pragma unroll
        for (int nj = 0; nj < 8; nj++)
            #pragma unroll
            for (int q = 0; q < 4; q++) acc[mi][nj][q] = 0.0f;

    auto issue = [&](int c, int buf) {
        const int seg = c >> 5;
        const int kk = (c & 31) * BK;
        const __nv_bfloat16* As = (seg < 2) ? aHi : aLo;
        const __nv_bfloat16* Bs = (seg == 1) ? bLo : bHi;
        cp16(smbase + buf * ASZ + (uint32_t)(arow * 40 + as4) * 2,
             As + (size_t)(bm + arow) * KDIM + kk + as4);
        #pragma unroll
        for (int i = 0; i < 2; i++) {
            int idx = tid + i * 512;
            int br = idx >> 2;
            int bs4 = (idx & 3) * 8;
            cp16(smbase + 2 * ASZ + buf * BSZ + (uint32_t)(br * 40 + bs4) * 2,
                 Bs + (size_t)(bn + br) * KDIM + kk + bs4);
        }
        asm volatile("cp.async.commit_group;" ::: "memory");
    };

    auto compute = [&](int buf) {
        const uint32_t aBase = smbase + buf * ASZ;
        const uint32_t bBase = smbase + 2 * ASZ + buf * BSZ;
        #pragma unroll
        for (int ks = 0; ks < 2; ks++) {
            uint32_t a[2][4];
            #pragma unroll
            for (int mi = 0; mi < 2; mi++) {
                uint32_t addr = aBase +
                    (uint32_t)((wm + mi * 16 + (l & 15)) * 40 + ks * 16 + (l >> 4) * 8) * 2;
                ldmx4(a[mi][0], a[mi][1], a[mi][2], a[mi][3], addr);
            }
            uint32_t b[4][4];
            const int mat = l >> 3;
            const int r8 = l & 7;
            #pragma unroll
            for (int p = 0; p < 4; p++) {
                int n = wn + p * 16 + ((mat >> 1) << 3) + r8;
                int kc = ks * 16 + ((mat & 1) << 3);
                uint32_t addr = bBase + (uint32_t)(n * 40 + kc) * 2;
                ldmx4(b[p][0], b[p][1], b[p][2], b[p][3], addr);
            }
            #pragma unroll
            for (int mi = 0; mi < 2; mi++)
                #pragma unroll
                for (int p = 0; p < 4; p++) {
                    mma16816(acc[mi][2 * p],     a[mi], b[p][0], b[p][1]);
                    mma16816(acc[mi][2 * p + 1], a[mi], b[p][2], b[p][3]);
                }
        }
    };

    issue(0, 0);
    for (int c = 0; c < CHUNKS; ++c) {
        if (c + 1 < CHUNKS) {
            issue(c + 1, (c + 1) & 1);
            asm volatile("cp.async.wait_group 1;" ::: "memory");
        } else {
            asm volatile("cp.async.wait_group 0;" ::: "memory");
        }
        __syncthreads();
        compute(c & 1);
        __syncthreads();
    }

    // Epilogue: acc -> C with bias
    #pragma unroll
    for (int mi = 0; mi < 2; mi++) {
        int r0 = bm + wm + mi * 16 + (l >> 2);
        #pragma unroll
        for (int nj = 0; nj < 8; nj++) {
            int col = bn + wn + nj * 8 + (l & 3) * 2;
            float2 bv = *(const float2*)&bias[col];
            float2 o0, o1;
            o0.x = acc[mi][nj][0] + bv.x;
            o0.y = acc[mi][nj][1] + bv.y;
            o1.x = acc[mi][nj][2] + bv.x;
            o1.y = acc[mi][nj][3] + bv.y;
            *(float2*)&C[(size_t)r0 * D_ + col] = o0;
            *(float2*)&C[(size_t)(r0 + 8) * D_ + col] = o1;
        }
    }
}

// ---------------------------------------------------------------------------
// Flash-style attention (round-1 passing version, unchanged)
// ---------------------------------------------------------------------------
__global__ __launch_bounds__(256) void attn_kernel(
    const float* __restrict__ Q, const float* __restrict__ K,
    const float* __restrict__ V, const int* __restrict__ mask,
    float* __restrict__ ctx)
{
    extern __shared__ float sm[];
    float* Qs  = sm;                 // [64][68]
    float* KsT = sm + 64 * 68;       // [64][68] transposed
    float* Vs  = sm + 2 * 64 * 68;   // [64][68]
    float* Ps  = sm + 3 * 64 * 68;   // [64][68]
    __shared__ int ms[64];

    const int tid = threadIdx.x;
    const int ty = tid >> 4;
    const int tx = tid & 15;
    const int b = blockIdx.z, h = blockIdx.y;
    const int q0 = blockIdx.x * 64;
    const float scale = 0.125f;

    #pragma unroll
    for (int it = 0; it < 4; ++it) {
        int idx = tid + it * 256;
        int r = idx >> 4;
        int c4 = (idx & 15) * 4;
        float4 v = *(const float4*)&Q[((size_t)(b * S_ + q0 + r)) * D_ + h * DK_ + c4];
        Qs[r * 68 + c4 + 0] = v.x * scale;
        Qs[r * 68 + c4 + 1] = v.y * scale;
        Qs[r * 68 + c4 + 2] = v.z * scale;
        Qs[r * 68 + c4 + 3] = v.w * scale;
    }

    float m_i[4], l_i[4], acc[4][4];
    #pragma unroll
    for (int i = 0; i < 4; i++) {
        m_i[i] = -1e30f; l_i[i] = 0.0f;
        #pragma unroll
        for (int j = 0; j < 4; j++) acc[i][j] = 0.0f;
    }

    for (int k0 = 0; k0 < S_; k0 += 64) {
        __syncthreads();
        #pragma unroll
        for (int it = 0; it < 4; ++it) {
            int idx = tid + it * 256;
            int r = idx >> 4;
            int c4 = (idx & 15) * 4;
            float4 kv = *(const float4*)&K[((size_t)(b * S_ + k0 + r)) * D_ + h * DK_ + c4];
            KsT[(c4 + 0) * 68 + r] = kv.x;
            KsT[(c4 + 1) * 68 + r] = kv.y;
            KsT[(c4 + 2) * 68 + r] = kv.z;
            KsT[(c4 + 3) * 68 + r] = kv.w;
            float4 vv = *(const float4*)&V[((size_t)(b * S_ + k0 + r)) * D_ + h * DK_ + c4];
            Vs[r * 68 + c4 + 0] = vv.x;
            Vs[r * 68 + c4 + 1] = vv.y;
            Vs[r * 68 + c4 + 2] = vv.z;
            Vs[r * 68 + c4 + 3] = vv.w;
        }
        if (tid < 64) ms[tid] = mask[b * S_ + k0 + tid];
        __syncthreads();

        float s[4][4];
        #pragma unroll
        for (int i = 0; i < 4; i++)
            #pragma unroll
            for (int j = 0; j < 4; j++) s[i][j] = 0.0f;

        #pragma unroll 4
        for (int d = 0; d < 64; ++d) {
            float4 bk = *(const float4*)&KsT[d * 68 + tx * 4];
            float bj[4] = {bk.x, bk.y, bk.z, bk.w};
            #pragma unroll
            for (int i = 0; i < 4; i++) {
                float aq = Qs[(ty * 4 + i) * 68 + d];
                #pragma unroll
                for (int j = 0; j < 4; j++)
                    s[i][j] = fmaf(aq, bj[j], s[i][j]);
            }
        }

        #pragma unroll
        for (int j = 0; j < 4; j++) {
            if (ms[tx * 4 + j] == 0) {
                #pragma unroll
                for (int i = 0; i < 4; i++) s[i][j] = -1e30f;
            }
        }

        float p[4][4];
        #pragma unroll
        for (int i = 0; i < 4; i++) {
            float rm = fmaxf(fmaxf(s[i][0], s[i][1]), fmaxf(s[i][2], s[i][3]));
            #pragma unroll
            for (int off = 1; off < 16; off <<= 1)
                rm = fmaxf(rm, __shfl_xor_sync(0xffffffffu, rm, off));
            float mnew = fmaxf(m_i[i], rm);
            float c = __expf(m_i[i] - mnew);
            m_i[i] = mnew;
            float rs = 0.0f;
            #pragma unroll
            for (int j = 0; j < 4; j++) {
                p[i][j] = __expf(s[i][j] - mnew);
                rs += p[i][j];
            }
            #pragma unroll
            for (int off = 1; off < 16; off <<= 1)
                rs += __shfl_xor_sync(0xffffffffu, rs, off);
            l_i[i] = l_i[i] * c + rs;
            #pragma unroll
            for (int j = 0; j < 4; j++) acc[i][j] *= c;
        }

        #pragma unroll
        for (int i = 0; i < 4; i++)
            #pragma unroll
            for (int j = 0; j < 4; j++)
                Ps[(ty * 4 + i) * 68 + tx * 4 + j] = p[i][j];
        __syncthreads();

        #pragma unroll 4
        for (int k = 0; k < 64; ++k) {
            float4 vv = *(const float4*)&Vs[k * 68 + tx * 4];
            float bv[4] = {vv.x, vv.y, vv.z, vv.w};
            #pragma unroll
            for (int i = 0; i < 4; i++) {
                float ap = Ps[(ty * 4 + i) * 68 + k];
                #pragma unroll
                for (int j = 0; j < 4; j++)
                    acc[i][j] = fmaf(ap, bv[j], acc[i][j]);
            }
        }
    }

    #pragma unroll
    for (int i = 0; i < 4; i++) {
        float inv = 1.0f / l_i[i];
        float4 v;
        v.x = acc[i][0] * inv; v.y = acc[i][1] * inv;
        v.z = acc[i][2] * inv; v.w = acc[i][3] * inv;
        *(float4*)&ctx[((size_t)(b * S_ + q0 + ty * 4 + i)) * D_ + h * DK_ + tx * 4] = v;
    }
}

// ---------------------------------------------------------------------------
extern "C" void kernel_launch(void* const* d_in, const int* in_sizes, int n_in,
                              void* d_out, int out_size)
{
    (void)in_sizes; (void)n_in; (void)out_size;
    const float* query = (const float*)d_in[0];
    const float* key   = (const float*)d_in[1];
    const float* value = (const float*)d_in[2];
    const int*   mask  = (const int*)d_in[3];
    const float* Wq = (const float*)d_in[4];
    const float* bq = (const float*)d_in[5];
    const float* Wk = (const float*)d_in[6];
    const float* bk = (const float*)d_in[7];
    const float* Wv = (const float*)d_in[8];
    const float* bv = (const float*)d_in[9];
    const float* Wo = (const float*)d_in[10];
    const float* bo = (const float*)d_in[11];
    float* out = (float*)d_out;

    float *Qb, *Kb, *Vb, *Cb;
    cudaGetSymbolAddress((void**)&Qb, g_Q);
    cudaGetSymbolAddress((void**)&Kb, g_K);
    cudaGetSymbolAddress((void**)&Vb, g_V);
    cudaGetSymbolAddress((void**)&Cb, g_ctx);
    __nv_bfloat16 *aHi, *aLo, *wHi, *wLo;
    cudaGetSymbolAddress((void**)&aHi, g_act_hi);
    cudaGetSymbolAddress((void**)&aLo, g_act_lo);
    cudaGetSymbolAddress((void**)&wHi, g_w_hi);
    cudaGetSymbolAddress((void**)&wLo, g_w_lo);

    const int actN4 = B_ * S_ * D_ / 4;   // 1048576
    const int wN4   = D_ * D_ / 4;        // 262144

    const size_t gemm_smem = 2 * (size_t)(ASZ + BSZ);   // 61440
    cudaFuncSetAttribute(gemm_mma, cudaFuncAttributeMaxDynamicSharedMemorySize,
                         (int)gemm_smem);
    dim3 ggrid(D_ / BN, (B_ * S_) / BM);   // (4, 32)
    dim3 gthr(512);

    // Q projection
    split_hl<<<actN4 / 256, 256>>>(query, aHi, aLo, actN4);
    split_hl<<<wN4 / 256, 256>>>(Wq, wHi, wLo, wN4);
    gemm_mma<<<ggrid, gthr, gemm_smem>>>(aHi, aLo, wHi, wLo, bq, Qb);
    // K projection
    split_hl<<<actN4 / 256, 256>>>(key, aHi, aLo, actN4);
    split_hl<<<wN4 / 256, 256>>>(Wk, wHi, wLo, wN4);
    gemm_mma<<<ggrid, gthr, gemm_smem>>>(aHi, aLo, wHi, wLo, bk, Kb);
    // V projection
    split_hl<<<actN4 / 256, 256>>>(value, aHi, aLo, actN4);
    split_hl<<<wN4 / 256, 256>>>(Wv, wHi, wLo, wN4);
    gemm_mma<<<ggrid, gthr, gemm_smem>>>(aHi, aLo, wHi, wLo, bv, Vb);

    // Attention
    static const size_t attn_smem = 4 * 64 * 68 * sizeof(float);  // 69632 B
    cudaFuncSetAttribute(attn_kernel, cudaFuncAttributeMaxDynamicSharedMemorySize,
                         (int)attn_smem);
    dim3 agrid(S_ / 64, H_, B_);     // (32, 16, 2)
    attn_kernel<<<agrid, 256, attn_smem>>>(Qb, Kb, Vb, mask, Cb);

    // Output projection
    split_hl<<<actN4 / 256, 256>>>(Cb, aHi, aLo, actN4);
    split_hl<<<wN4 / 256, 256>>>(Wo, wHi, wLo, wN4);
    gemm_mma<<<ggrid, gthr, gemm_smem>>>(aHi, aLo, wHi, wLo, bo, out);
}

// round 4
// speedup vs baseline: 2.2774x; 1.8411x over previous
#include <cuda_runtime.h>
#include <cuda_bf16.h>
#include <math.h>
#include <stdint.h>

// Problem constants
#define B_  2
#define S_  2048
#define D_  1024
#define H_  16
#define DK_ 64

// GEMM tiling
#define BM 128
#define BN 256
#define BK 32
#define KDIM 1024
#define CHUNKS 96           // 3 * KDIM / BK  (hi*hi, hi*lo, lo*hi segments)
#define ASZ (BM * 40 * 2)   // bf16 tile 128 x 32, padded stride 40
#define BSZ (BN * 40 * 2)

// Attention smem layout
#define SK 72               // padded stride (elems) for 64-wide bf16 tiles
#define TILE_B (128 * SK * 2)          // 18432 bytes per tile
#define QH_OFF 0
#define QL_OFF TILE_B
#define KV_OFF(buf, t) (2 * TILE_B + (buf) * 4 * TILE_B + (t) * TILE_B)
#define MS_OFF (10 * TILE_B)           // 184320
#define ATTN_SMEM (MS_OFF + 1024)      // 185344

// Scratch (device globals: no allocations allowed)
__device__ __nv_bfloat16 g_qh[B_*S_*D_], g_ql[B_*S_*D_];
__device__ __nv_bfloat16 g_kh[B_*S_*D_], g_kl[B_*S_*D_];
__device__ __nv_bfloat16 g_vh[B_*S_*D_], g_vl[B_*S_*D_];
__device__ __nv_bfloat16 g_ch[B_*S_*D_], g_cl[B_*S_*D_];
__device__ __nv_bfloat16 g_act_hi[B_*S_*D_];
__device__ __nv_bfloat16 g_act_lo[B_*S_*D_];
__device__ __nv_bfloat16 g_w_hi[D_*D_];
__device__ __nv_bfloat16 g_w_lo[D_*D_];

// ===========================================================================
// Helpers
// ===========================================================================
__device__ __forceinline__ uint32_t smem_u32(const void* p) {
    uint32_t a;
    asm("{ .reg .u64 t; cvta.to.shared.u64 t, %1; cvt.u32.u64 %0, t; }"
        : "=r"(a) : "l"(p));
    return a;
}

__device__ __forceinline__ void cp16(uint32_t dst, const void* src) {
    asm volatile("cp.async.cg.shared.global [%0], [%1], 16;"
                 :: "r"(dst), "l"(src));
}
__device__ __forceinline__ void cp4(uint32_t dst, const void* src) {
    asm volatile("cp.async.ca.shared.global [%0], [%1], 4;"
                 :: "r"(dst), "l"(src));
}

__device__ __forceinline__ void ldmx4(uint32_t& r0, uint32_t& r1,
                                      uint32_t& r2, uint32_t& r3, uint32_t addr) {
    asm volatile("ldmatrix.sync.aligned.m8n8.x4.shared.b16 {%0,%1,%2,%3}, [%4];"
                 : "=r"(r0), "=r"(r1), "=r"(r2), "=r"(r3) : "r"(addr));
}
__device__ __forceinline__ void ldmx4t(uint32_t& r0, uint32_t& r1,
                                       uint32_t& r2, uint32_t& r3, uint32_t addr) {
    asm volatile("ldmatrix.sync.aligned.m8n8.x4.trans.shared.b16 {%0,%1,%2,%3}, [%4];"
                 : "=r"(r0), "=r"(r1), "=r"(r2), "=r"(r3) : "r"(addr));
}

__device__ __forceinline__ void mma16816(float* c, const uint32_t* a,
                                         uint32_t b0, uint32_t b1) {
    asm volatile(
        "mma.sync.aligned.m16n8k16.row.col.f32.bf16.bf16.f32 "
        "{%0,%1,%2,%3}, {%4,%5,%6,%7}, {%8,%9}, {%0,%1,%2,%3};"
        : "+f"(c[0]), "+f"(c[1]), "+f"(c[2]), "+f"(c[3])
        : "r"(a[0]), "r"(a[1]), "r"(a[2]), "r"(a[3]), "r"(b0), "r"(b1));
}

__device__ __forceinline__ uint32_t pack2(unsigned short a, unsigned short b) {
    return (uint32_t)a | ((uint32_t)b << 16);
}
// packed = {lo_elem, hi_elem} bf16x2 (first src -> high half per PTX)
__device__ __forceinline__ uint32_t cvt2bf(float hi_elem, float lo_elem) {
    uint32_t r;
    asm("cvt.rn.bf16x2.f32 %0, %1, %2;" : "=r"(r) : "f"(hi_elem), "f"(lo_elem));
    return r;
}
__device__ __forceinline__ float bflo(uint32_t p) { return __uint_as_float(p << 16); }
__device__ __forceinline__ float bfhi(uint32_t p) { return __uint_as_float(p & 0xFFFF0000u); }

// ===========================================================================
// Split fp32 -> (hi, lo) bf16 pair
// ===========================================================================
__global__ __launch_bounds__(256) void split_hl(
    const float* __restrict__ x, __nv_bfloat16* __restrict__ hi,
    __nv_bfloat16* __restrict__ lo, int n4)
{
    int i = blockIdx.x * blockDim.x + threadIdx.x;
    if (i >= n4) return;
    float4 v = ((const float4*)x)[i];
    float f[4] = {v.x, v.y, v.z, v.w};
    unsigned short h[4], l[4];
    #pragma unroll
    for (int j = 0; j < 4; j++) {
        __nv_bfloat16 bh = __float2bfloat16(f[j]);
        float r = f[j] - __bfloat162float(bh);
        __nv_bfloat16 bl = __float2bfloat16(r);
        h[j] = __bfloat16_as_ushort(bh);
        l[j] = __bfloat16_as_ushort(bl);
    }
    ((uint2*)hi)[i] = make_uint2(pack2(h[0], h[1]), pack2(h[2], h[3]));
    ((uint2*)lo)[i] = make_uint2(pack2(l[0], l[1]), pack2(l[2], l[3]));
}

// ===========================================================================
// Tensor-core GEMM (NT + bias) via mma.sync bf16, hi/lo concat-K (K'=3072).
// SPLIT=true  -> write bf16 hi/lo pair (for Q/K/V)
// SPLIT=false -> write fp32 (final output)
// ===========================================================================
template<bool SPLIT>
__global__ __launch_bounds__(512) void gemm_mma(
    const __nv_bfloat16* __restrict__ aHi, const __nv_bfloat16* __restrict__ aLo,
    const __nv_bfloat16* __restrict__ bHi, const __nv_bfloat16* __restrict__ bLo,
    const float* __restrict__ bias, float* __restrict__ Cf,
    __nv_bfloat16* __restrict__ Chi, __nv_bfloat16* __restrict__ Clo)
{
    extern __shared__ char dynsm[];
    const uint32_t smbase = smem_u32(dynsm);
    const int tid = threadIdx.x;
    const int l = tid & 31;
    const int wid = tid >> 5;
    const int wm = (wid & 3) * 32;
    const int wn = (wid >> 2) * 64;
    const int bm = blockIdx.y * BM;
    const int bn = blockIdx.x * BN;

    const int arow = tid >> 2;
    const int as4 = (tid & 3) * 8;

    float acc[2][8][4];
    #pragma unroll
    for (int mi = 0; mi < 2; mi++)
        #pragma unroll
        for (int nj = 0; nj < 8; nj++)
            #pragma unroll
            for (int q = 0; q < 4; q++) acc[mi][nj][q] = 0.0f;

    auto issue = [&](int c, int buf) {
        const int seg = c >> 5;
        const int kk = (c & 31) * BK;
        const __nv_bfloat16* As = (seg < 2) ? aHi : aLo;
        const __nv_bfloat16* Bs = (seg == 1) ? bLo : bHi;
        cp16(smbase + buf * ASZ + (uint32_t)(arow * 40 + as4) * 2,
             As + (size_t)(bm + arow) * KDIM + kk + as4);
        #pragma unroll
        for (int i = 0; i < 2; i++) {
            int idx = tid + i * 512;
            int br = idx >> 2;
            int bs4 = (idx & 3) * 8;
            cp16(smbase + 2 * ASZ + buf * BSZ + (uint32_t)(br * 40 + bs4) * 2,
                 Bs + (size_t)(bn + br) * KDIM + kk + bs4);
        }
        asm volatile("cp.async.commit_group;" ::: "memory");
    };

    auto compute = [&](int buf) {
        const uint32_t aBase = smbase + buf * ASZ;
        const uint32_t bBase = smbase + 2 * ASZ + buf * BSZ;
        #pragma unroll
        for (int ks = 0; ks < 2; ks++) {
            uint32_t a[2][4];
            #pragma unroll
            for (int mi = 0; mi < 2; mi++) {
                uint32_t addr = aBase +
                    (uint32_t)((wm + mi * 16 + (l & 15)) * 40 + ks * 16 + (l >> 4) * 8) * 2;
                ldmx4(a[mi][0], a[mi][1], a[mi][2], a[mi][3], addr);
            }
            uint32_t b[4][4];
            const int mat = l >> 3;
            const int r8 = l & 7;
            #pragma unroll
            for (int p = 0; p < 4; p++) {
                int n = wn + p * 16 + ((mat >> 1) << 3) + r8;
                int kc = ks * 16 + ((mat & 1) << 3);
                uint32_t addr = bBase + (uint32_t)(n * 40 + kc) * 2;
                ldmx4(b[p][0], b[p][1], b[p][2], b[p][3], addr);
            }
            #pragma unroll
            for (int mi = 0; mi < 2; mi++)
                #pragma unroll
                for (int p = 0; p < 4; p++) {
                    mma16816(acc[mi][2 * p],     a[mi], b[p][0], b[p][1]);
                    mma16816(acc[mi][2 * p + 1], a[mi], b[p][2], b[p][3]);
                }
        }
    };

    issue(0, 0);
    for (int c = 0; c < CHUNKS; ++c) {
        if (c + 1 < CHUNKS) {
            issue(c + 1, (c + 1) & 1);
            asm volatile("cp.async.wait_group 1;" ::: "memory");
        } else {
            asm volatile("cp.async.wait_group 0;" ::: "memory");
        }
        __syncthreads();
        compute(c & 1);
        __syncthreads();
    }

    #pragma unroll
    for (int mi = 0; mi < 2; mi++) {
        int r0 = bm + wm + mi * 16 + (l >> 2);
        #pragma unroll
        for (int nj = 0; nj < 8; nj++) {
            int col = bn + wn + nj * 8 + (l & 3) * 2;
            float2 bv = *(const float2*)&bias[col];
            float v0 = acc[mi][nj][0] + bv.x;
            float v1 = acc[mi][nj][1] + bv.y;
            float v2 = acc[mi][nj][2] + bv.x;
            float v3 = acc[mi][nj][3] + bv.y;
            if (SPLIT) {
                uint32_t ph = cvt2bf(v1, v0);
                uint32_t pl = cvt2bf(v1 - bfhi(ph), v0 - bflo(ph));
                *(uint32_t*)&Chi[(size_t)r0 * D_ + col] = ph;
                *(uint32_t*)&Clo[(size_t)r0 * D_ + col] = pl;
                ph = cvt2bf(v3, v2);
                pl = cvt2bf(v3 - bfhi(ph), v2 - bflo(ph));
                *(uint32_t*)&Chi[(size_t)(r0 + 8) * D_ + col] = ph;
                *(uint32_t*)&Clo[(size_t)(r0 + 8) * D_ + col] = pl;
            } else {
                *(float2*)&Cf[(size_t)r0 * D_ + col] = make_float2(v0, v1);
                *(float2*)&Cf[(size_t)(r0 + 8) * D_ + col] = make_float2(v2, v3);
            }
        }
    }
}

// ===========================================================================
// Tensor-core flash attention (bf16 hi/lo pairs, fp32 softmax).
// CTA = (b, h, 128-query tile), 8 warps; warp = 16 q-rows x 128 keys.
// ===========================================================================
__global__ __launch_bounds__(256) void attn_mma(
    const __nv_bfloat16* __restrict__ qHi, const __nv_bfloat16* __restrict__ qLo,
    const __nv_bfloat16* __restrict__ kHi, const __nv_bfloat16* __restrict__ kLo,
    const __nv_bfloat16* __restrict__ vHi, const __nv_bfloat16* __restrict__ vLo,
    const int* __restrict__ mask,
    __nv_bfloat16* __restrict__ cHi, __nv_bfloat16* __restrict__ cLo)
{
    extern __shared__ char dynsm[];
    const uint32_t smb = smem_u32(dynsm);
    const int tid = threadIdx.x;
    const int w = tid >> 5, l = tid & 31;
    const int b = blockIdx.z, h = blockIdx.y;
    const int q0 = blockIdx.x * 128;
    const size_t bS = (size_t)b * S_;
    const int hd = h * DK_;

    auto load_tile = [&](const __nv_bfloat16* g, uint32_t off, int tok0) {
        #pragma unroll
        for (int t = 0; t < 4; t++) {
            int idx = tid + t * 256;
            int row = idx >> 3, seg = (idx & 7) * 8;
            cp16(smb + off + (uint32_t)(row * SK + seg) * 2,
                 g + (bS + tok0 + row) * D_ + hd + seg);
        }
    };
    auto load_kv = [&](int kt, int buf) {
        int tok0 = kt * 128;
        load_tile(kHi, KV_OFF(buf, 0), tok0);
        load_tile(kLo, KV_OFF(buf, 1), tok0);
        load_tile(vHi, KV_OFF(buf, 2), tok0);
        load_tile(vLo, KV_OFF(buf, 3), tok0);
        if (tid < 128) cp4(smb + MS_OFF + (uint32_t)(buf * 128 + tid) * 4,
                           mask + b * S_ + tok0 + tid);
    };

    load_tile(qHi, QH_OFF, q0);
    load_tile(qLo, QL_OFF, q0);
    load_kv(0, 0);
    asm volatile("cp.async.commit_group;" ::: "memory");

    float Oacc[8][4];
    #pragma unroll
    for (int nf = 0; nf < 8; nf++)
        #pragma unroll
        for (int q = 0; q < 4; q++) Oacc[nf][q] = 0.0f;
    float mrun0 = -1e30f, mrun1 = -1e30f, lrun0 = 0.0f, lrun1 = 0.0f;

    const uint32_t a_off = (uint32_t)((w * 16 + (l & 15)) * SK + ((l >> 4) << 3)) * 2;
    const int bmat = l >> 3, br8 = l & 7;

    for (int kt = 0; kt < 16; kt++) {
        const int buf = kt & 1;
        if (kt < 15) {
            load_kv(kt + 1, buf ^ 1);
            asm volatile("cp.async.commit_group;" ::: "memory");
            asm volatile("cp.async.wait_group 1;" ::: "memory");
        } else {
            asm volatile("cp.async.wait_group 0;" ::: "memory");
        }
        __syncthreads();

        const uint32_t KhB = smb + KV_OFF(buf, 0), KlB = smb + KV_OFF(buf, 1);
        const uint32_t VhB = smb + KV_OFF(buf, 2), VlB = smb + KV_OFF(buf, 3);
        const int* ms = (const int*)(dynsm + MS_OFF + buf * 512);

        float sacc[16][4];
        #pragma unroll
        for (int f = 0; f < 16; f++)
            #pragma unroll
            for (int q = 0; q < 4; q++) sacc[f][q] = 0.0f;

        // ---- S = Q K^T (3-pass hi/lo) ----
        #pragma unroll
        for (int kc = 0; kc < 4; kc++) {
            uint32_t aH[4], aL[4];
            ldmx4(aH[0], aH[1], aH[2], aH[3], smb + QH_OFF + a_off + kc * 32);
            ldmx4(aL[0], aL[1], aL[2], aL[3], smb + QL_OFF + a_off + kc * 32);
            #pragma unroll
            for (int np = 0; np < 8; np++) {
                uint32_t badr = (uint32_t)((np * 16 + ((bmat >> 1) << 3) + br8) * SK
                                           + kc * 16 + ((bmat & 1) << 3)) * 2;
                uint32_t bh0, bh1, bh2, bh3, bl0, bl1, bl2, bl3;
                ldmx4(bh0, bh1, bh2, bh3, KhB + badr);
                ldmx4(bl0, bl1, bl2, bl3, KlB + badr);
                mma16816(sacc[2 * np],     aH, bh0, bh1);
                mma16816(sacc[2 * np + 1], aH, bh2, bh3);
                mma16816(sacc[2 * np],     aH, bl0, bl1);
                mma16816(sacc[2 * np + 1], aH, bl2, bl3);
                mma16816(sacc[2 * np],     aL, bh0, bh1);
                mma16816(sacc[2 * np + 1], aL, bh2, bh3);
            }
        }

        // ---- scale + mask + online softmax (rows l>>2 and +8) ----
        float mx0 = -1e30f, mx1 = -1e30f;
        #pragma unroll
        for (int f = 0; f < 16; f++) {
            int c0 = f * 8 + (l & 3) * 2;
            int mk0 = ms[c0], mk1 = ms[c0 + 1];
            float t0 = mk0 ? sacc[f][0] * 0.125f : -1e30f;
            float t1 = mk1 ? sacc[f][1] * 0.125f : -1e30f;
            float t2 = mk0 ? sacc[f][2] * 0.125f : -1e30f;
            float t3 = mk1 ? sacc[f][3] * 0.125f : -1e30f;
            sacc[f][0] = t0; sacc[f][1] = t1; sacc[f][2] = t2; sacc[f][3] = t3;
            mx0 = fmaxf(mx0, fmaxf(t0, t1));
            mx1 = fmaxf(mx1, fmaxf(t2, t3));
        }
        mx0 = fmaxf(mx0, __shfl_xor_sync(0xffffffffu, mx0, 1));
        mx0 = fmaxf(mx0, __shfl_xor_sync(0xffffffffu, mx0, 2));
        mx1 = fmaxf(mx1, __shfl_xor_sync(0xffffffffu, mx1, 1));
        mx1 = fmaxf(mx1, __shfl_xor_sync(0xffffffffu, mx1, 2));
        float mn0 = fmaxf(mrun0, mx0), mn1 = fmaxf(mrun1, mx1);
        float cor0 = __expf(mrun0 - mn0), cor1 = __expf(mrun1 - mn1);
        mrun0 = mn0; mrun1 = mn1;
        float sum0 = 0.0f, sum1 = 0.0f;
        #pragma unroll
        for (int f = 0; f < 16; f++) {
            float p0 = __expf(sacc[f][0] - mn0);
            float p1 = __expf(sacc[f][1] - mn0);
            float p2 = __expf(sacc[f][2] - mn1);
            float p3 = __expf(sacc[f][3] - mn1);
            sacc[f][0] = p0; sacc[f][1] = p1; sacc[f][2] = p2; sacc[f][3] = p3;
            sum0 += p0 + p1; sum1 += p2 + p3;
        }
        sum0 += __shfl_xor_sync(0xffffffffu, sum0, 1);
        sum0 += __shfl_xor_sync(0xffffffffu, sum0, 2);
        sum1 += __shfl_xor_sync(0xffffffffu, sum1, 1);
        sum1 += __shfl_xor_sync(0xffffffffu, sum1, 2);
        lrun0 = lrun0 * cor0 + sum0;
        lrun1 = lrun1 * cor1 + sum1;
        #pragma unroll
        for (int nf = 0; nf < 8; nf++) {
            Oacc[nf][0] *= cor0; Oacc[nf][1] *= cor0;
            Oacc[nf][2] *= cor1; Oacc[nf][3] *= cor1;
        }

        // ---- O += P V (3-pass hi/lo), P frags packed from sacc on the fly ----
        #pragma unroll
        for (int kc2 = 0; kc2 < 8; kc2++) {
            const float* f0 = sacc[2 * kc2];
            const float* f1 = sacc[2 * kc2 + 1];
            uint32_t aH2[4], aL2[4];
            aH2[0] = cvt2bf(f0[1], f0[0]);
            aH2[1] = cvt2bf(f0[3], f0[2]);
            aH2[2] = cvt2bf(f1[1], f1[0]);
            aH2[3] = cvt2bf(f1[3], f1[2]);
            aL2[0] = cvt2bf(f0[1] - bfhi(aH2[0]), f0[0] - bflo(aH2[0]));
            aL2[1] = cvt2bf(f0[3] - bfhi(aH2[1]), f0[2] - bflo(aH2[1]));
            aL2[2] = cvt2bf(f1[1] - bfhi(aH2[2]), f1[0] - bflo(aH2[2]));
            aL2[3] = cvt2bf(f1[3] - bfhi(aH2[3]), f1[2] - bflo(aH2[3]));
            #pragma unroll
            for (int nf = 0; nf < 4; nf++) {
                uint32_t vadr = (uint32_t)((kc2 * 16 + (l & 15)) * SK
                                           + nf * 16 + ((l >> 4) << 3)) * 2;
                uint32_t vh0, vh1, vh2, vh3, vl0, vl1, vl2, vl3;
                ldmx4t(vh0, vh1, vh2, vh3, VhB + vadr);
                ldmx4t(vl0, vl1, vl2, vl3, VlB + vadr);
                mma16816(Oacc[2 * nf],     aH2, vh0, vh1);
                mma16816(Oacc[2 * nf + 1], aH2, vh2, vh3);
                mma16816(Oacc[2 * nf],     aH2, vl0, vl1);
                mma16816(Oacc[2 * nf + 1], aH2, vl2, vl3);
                mma16816(Oacc[2 * nf],     aL2, vh0, vh1);
                mma16816(Oacc[2 * nf + 1], aL2, vh2, vh3);
            }
        }
        __syncthreads();
    }

    // ---- epilogue: normalize, split hi/lo, write ctx ----
    const float inv0 = 1.0f / lrun0;
    const float inv1 = 1.0f / lrun1;
    const int r0 = q0 + w * 16 + (l >> 2);
    #pragma unroll
    for (int nf = 0; nf < 8; nf++) {
        int col = hd + nf * 8 + (l & 3) * 2;
        float v0 = Oacc[nf][0] * inv0, v1 = Oacc[nf][1] * inv0;
        uint32_t ph = cvt2bf(v1, v0);
        uint32_t pl = cvt2bf(v1 - bfhi(ph), v0 - bflo(ph));
        *(uint32_t*)&cHi[(bS + r0) * D_ + col] = ph;
        *(uint32_t*)&cLo[(bS + r0) * D_ + col] = pl;
        float v2 = Oacc[nf][2] * inv1, v3 = Oacc[nf][3] * inv1;
        ph = cvt2bf(v3, v2);
        pl = cvt2bf(v3 - bfhi(ph), v2 - bflo(ph));
        *(uint32_t*)&cHi[(bS + r0 + 8) * D_ + col] = ph;
        *(uint32_t*)&cLo[(bS + r0 + 8) * D_ + col] = pl;
    }
}

// ---------------------------------------------------------------------------
extern "C" void kernel_launch(void* const* d_in, const int* in_sizes, int n_in,
                              void* d_out, int out_size)
{
    (void)in_sizes; (void)n_in; (void)out_size;
    const float* query = (const float*)d_in[0];
    const float* key   = (const float*)d_in[1];
    const float* value = (const float*)d_in[2];
    const int*   mask  = (const int*)d_in[3];
    const float* Wq = (const float*)d_in[4];
    const float* bq = (const float*)d_in[5];
    const float* Wk = (const float*)d_in[6];
    const float* bk = (const float*)d_in[7];
    const float* Wv = (const float*)d_in[8];
    const float* bv = (const float*)d_in[9];
    const float* Wo = (const float*)d_in[10];
    const float* bo = (const float*)d_in[11];
    float* out = (float*)d_out;

    __nv_bfloat16 *qh, *ql, *kh, *kl, *vh, *vl, *ch, *cl, *aHi, *aLo, *wHi, *wLo;
    cudaGetSymbolAddress((void**)&qh, g_qh);
    cudaGetSymbolAddress((void**)&ql, g_ql);
    cudaGetSymbolAddress((void**)&kh, g_kh);
    cudaGetSymbolAddress((void**)&kl, g_kl);
    cudaGetSymbolAddress((void**)&vh, g_vh);
    cudaGetSymbolAddress((void**)&vl, g_vl);
    cudaGetSymbolAddress((void**)&ch, g_ch);
    cudaGetSymbolAddress((void**)&cl, g_cl);
    cudaGetSymbolAddress((void**)&aHi, g_act_hi);
    cudaGetSymbolAddress((void**)&aLo, g_act_lo);
    cudaGetSymbolAddress((void**)&wHi, g_w_hi);
    cudaGetSymbolAddress((void**)&wLo, g_w_lo);

    const int actN4 = B_ * S_ * D_ / 4;
    const int wN4   = D_ * D_ / 4;

    const size_t gemm_smem = 2 * (size_t)(ASZ + BSZ);
    cudaFuncSetAttribute(gemm_mma<true>, cudaFuncAttributeMaxDynamicSharedMemorySize,
                         (int)gemm_smem);
    cudaFuncSetAttribute(gemm_mma<false>, cudaFuncAttributeMaxDynamicSharedMemorySize,
                         (int)gemm_smem);
    dim3 ggrid(D_ / BN, (B_ * S_) / BM);
    dim3 gthr(512);

    // Q projection -> bf16 hi/lo
    split_hl<<<actN4 / 256, 256>>>(query, aHi, aLo, actN4);
    split_hl<<<wN4 / 256, 256>>>(Wq, wHi, wLo, wN4);
    gemm_mma<true><<<ggrid, gthr, gemm_smem>>>(aHi, aLo, wHi, wLo, bq, nullptr, qh, ql);
    // K projection
    split_hl<<<actN4 / 256, 256>>>(key, aHi, aLo, actN4);
    split_hl<<<wN4 / 256, 256>>>(Wk, wHi, wLo, wN4);
    gemm_mma<true><<<ggrid, gthr, gemm_smem>>>(aHi, aLo, wHi, wLo, bk, nullptr, kh, kl);
    // V projection
    split_hl<<<actN4 / 256, 256>>>(value, aHi, aLo, actN4);
    split_hl<<<wN4 / 256, 256>>>(Wv, wHi, wLo, wN4);
    gemm_mma<true><<<ggrid, gthr, gemm_smem>>>(aHi, aLo, wHi, wLo, bv, nullptr, vh, vl);

    // Attention (tensor-core flash)
    cudaFuncSetAttribute(attn_mma, cudaFuncAttributeMaxDynamicSharedMemorySize,
                         ATTN_SMEM);
    dim3 agrid(S_ / 128, H_, B_);
    attn_mma<<<agrid, 256, ATTN_SMEM>>>(qh, ql, kh, kl, vh, vl, mask, ch, cl);

    // Output projection (fp32 out)
    split_hl<<<wN4 / 256, 256>>>(Wo, wHi, wLo, wN4);
    gemm_mma<false><<<ggrid, gthr, gemm_smem>>>(ch, cl, wHi, wLo, bo, out, nullptr, nullptr);
}

// round 5
// speedup vs baseline: 2.6096x; 1.1459x over previous
#include <cuda_runtime.h>
#include <cuda_bf16.h>
#include <math.h>
#include <stdint.h>

// Problem constants
#define B_  2
#define S_  2048
#define D_  1024
#define H_  16
#define DK_ 64

// GEMM tiling
#define BM 128
#define BN 256
#define BK 32
#define KDIM 1024
#define CHUNKS 32
#define A_T 10240            // 128 x 40 x 2B
#define B_T 20480            // 256 x 40 x 2B
#define BUF (2 * A_T + 2 * B_T)          // 61440
#define GEMM_SMEM (3 * BUF)              // 184320

// Attention smem layout
#define SK 72
#define TILE_B (128 * SK * 2)
#define QH_OFF 0
#define QL_OFF TILE_B
#define KV_OFF(buf, t) (2 * TILE_B + (buf) * 4 * TILE_B + (t) * TILE_B)
#define MS_OFF (10 * TILE_B)
#define ATTN_SMEM (MS_OFF + 1024)

// Scratch (device globals)
__device__ __nv_bfloat16 g_qh[B_*S_*D_], g_ql[B_*S_*D_];
__device__ __nv_bfloat16 g_kh[B_*S_*D_], g_kl[B_*S_*D_];
__device__ __nv_bfloat16 g_vh[B_*S_*D_], g_vl[B_*S_*D_];
__device__ __nv_bfloat16 g_ch[B_*S_*D_], g_cl[B_*S_*D_];
__device__ __nv_bfloat16 g_aqh[B_*S_*D_], g_aql[B_*S_*D_];
__device__ __nv_bfloat16 g_akh[B_*S_*D_], g_akl[B_*S_*D_];
__device__ __nv_bfloat16 g_avh[B_*S_*D_], g_avl[B_*S_*D_];
__device__ __nv_bfloat16 g_wqh[D_*D_], g_wql[D_*D_];
__device__ __nv_bfloat16 g_wkh[D_*D_], g_wkl[D_*D_];
__device__ __nv_bfloat16 g_wvh[D_*D_], g_wvl[D_*D_];
__device__ __nv_bfloat16 g_woh[D_*D_], g_wol[D_*D_];

// ===========================================================================
// Helpers
// ===========================================================================
__device__ __forceinline__ uint32_t smem_u32(const void* p) {
    uint32_t a;
    asm("{ .reg .u64 t; cvta.to.shared.u64 t, %1; cvt.u32.u64 %0, t; }"
        : "=r"(a) : "l"(p));
    return a;
}
__device__ __forceinline__ void cp16(uint32_t dst, const void* src) {
    asm volatile("cp.async.cg.shared.global [%0], [%1], 16;" :: "r"(dst), "l"(src));
}
__device__ __forceinline__ void cp4(uint32_t dst, const void* src) {
    asm volatile("cp.async.ca.shared.global [%0], [%1], 4;" :: "r"(dst), "l"(src));
}
__device__ __forceinline__ void ldmx4(uint32_t& r0, uint32_t& r1,
                                      uint32_t& r2, uint32_t& r3, uint32_t addr) {
    asm volatile("ldmatrix.sync.aligned.m8n8.x4.shared.b16 {%0,%1,%2,%3}, [%4];"
                 : "=r"(r0), "=r"(r1), "=r"(r2), "=r"(r3) : "r"(addr));
}
__device__ __forceinline__ void ldmx4t(uint32_t& r0, uint32_t& r1,
                                       uint32_t& r2, uint32_t& r3, uint32_t addr) {
    asm volatile("ldmatrix.sync.aligned.m8n8.x4.trans.shared.b16 {%0,%1,%2,%3}, [%4];"
                 : "=r"(r0), "=r"(r1), "=r"(r2), "=r"(r3) : "r"(addr));
}
__device__ __forceinline__ void mma16816(float* c, const uint32_t* a,
                                         uint32_t b0, uint32_t b1) {
    asm volatile(
        "mma.sync.aligned.m16n8k16.row.col.f32.bf16.bf16.f32 "
        "{%0,%1,%2,%3}, {%4,%5,%6,%7}, {%8,%9}, {%0,%1,%2,%3};"
        : "+f"(c[0]), "+f"(c[1]), "+f"(c[2]), "+f"(c[3])
        : "r"(a[0]), "r"(a[1]), "r"(a[2]), "r"(a[3]), "r"(b0), "r"(b1));
}
__device__ __forceinline__ uint32_t pack2(unsigned short a, unsigned short b) {
    return (uint32_t)a | ((uint32_t)b << 16);
}
__device__ __forceinline__ uint32_t cvt2bf(float hi_elem, float lo_elem) {
    uint32_t r;
    asm("cvt.rn.bf16x2.f32 %0, %1, %2;" : "=r"(r) : "f"(hi_elem), "f"(lo_elem));
    return r;
}
__device__ __forceinline__ float bflo(uint32_t p) { return __uint_as_float(p << 16); }
__device__ __forceinline__ float bfhi(uint32_t p) { return __uint_as_float(p & 0xFFFF0000u); }

// ===========================================================================
// Split kernels (batched)
// ===========================================================================
__device__ __forceinline__ void split_one(const float* x, __nv_bfloat16* hi,
                                          __nv_bfloat16* lo, int i) {
    float4 v = ((const float4*)x)[i];
    float f[4] = {v.x, v.y, v.z, v.w};
    unsigned short h[4], l[4];
    #pragma unroll
    for (int j = 0; j < 4; j++) {
        __nv_bfloat16 bh = __float2bfloat16(f[j]);
        float r = f[j] - __bfloat162float(bh);
        h[j] = __bfloat16_as_ushort(bh);
        l[j] = __bfloat16_as_ushort(__float2bfloat16(r));
    }
    ((uint2*)hi)[i] = make_uint2(pack2(h[0], h[1]), pack2(h[2], h[3]));
    ((uint2*)lo)[i] = make_uint2(pack2(l[0], l[1]), pack2(l[2], l[3]));
}

__global__ __launch_bounds__(256) void split_acts(
    const float* __restrict__ q, const float* __restrict__ k, const float* __restrict__ v,
    __nv_bfloat16* qh, __nv_bfloat16* ql, __nv_bfloat16* kh, __nv_bfloat16* kl,
    __nv_bfloat16* vh, __nv_bfloat16* vl)
{
    int i = blockIdx.x * 256 + threadIdx.x;
    int z = blockIdx.y;
    const float* x = (z == 0) ? q : (z == 1) ? k : v;
    __nv_bfloat16* hi = (z == 0) ? qh : (z == 1) ? kh : vh;
    __nv_bfloat16* lo = (z == 0) ? ql : (z == 1) ? kl : vl;
    split_one(x, hi, lo, i);
}

__global__ __launch_bounds__(256) void split_weights(
    const float* __restrict__ w0, const float* __restrict__ w1,
    const float* __restrict__ w2, const float* __restrict__ w3,
    __nv_bfloat16* h0, __nv_bfloat16* l0, __nv_bfloat16* h1, __nv_bfloat16* l1,
    __nv_bfloat16* h2, __nv_bfloat16* l2, __nv_bfloat16* h3, __nv_bfloat16* l3)
{
    int i = blockIdx.x * 256 + threadIdx.x;
    int z = blockIdx.y;
    const float* x = (z == 0) ? w0 : (z == 1) ? w1 : (z == 2) ? w2 : w3;
    __nv_bfloat16* hi = (z == 0) ? h0 : (z == 1) ? h1 : (z == 2) ? h2 : h3;
    __nv_bfloat16* lo = (z == 0) ? l0 : (z == 1) ? l1 : (z == 2) ? l2 : l3;
    split_one(x, hi, lo, i);
}

// ===========================================================================
// GEMM (NT + bias), 3-product hi/lo per K-chunk, 3-stage cp.async, z-batched.
// ===========================================================================
template<bool SPLIT>
__global__ __launch_bounds__(512) void gemm3(
    const __nv_bfloat16* __restrict__ a0h, const __nv_bfloat16* __restrict__ a0l,
    const __nv_bfloat16* __restrict__ w0h, const __nv_bfloat16* __restrict__ w0l,
    const float* __restrict__ bias0,
    const __nv_bfloat16* __restrict__ a1h, const __nv_bfloat16* __restrict__ a1l,
    const __nv_bfloat16* __restrict__ w1h, const __nv_bfloat16* __restrict__ w1l,
    const float* __restrict__ bias1,
    const __nv_bfloat16* __restrict__ a2h, const __nv_bfloat16* __restrict__ a2l,
    const __nv_bfloat16* __restrict__ w2h, const __nv_bfloat16* __restrict__ w2l,
    const float* __restrict__ bias2,
    float* __restrict__ Cf,
    __nv_bfloat16* __restrict__ C0h, __nv_bfloat16* __restrict__ C0l,
    __nv_bfloat16* __restrict__ C1h, __nv_bfloat16* __restrict__ C1l,
    __nv_bfloat16* __restrict__ C2h, __nv_bfloat16* __restrict__ C2l)
{
    extern __shared__ char dynsm[];
    const uint32_t smb = smem_u32(dynsm);
    const int tid = threadIdx.x;
    const int l = tid & 31;
    const int wid = tid >> 5;
    const int wm = (wid & 3) * 32;
    const int wn = (wid >> 2) * 64;
    const int bm = blockIdx.y * BM;
    const int bn = blockIdx.x * BN;
    const int z = blockIdx.z;

    const __nv_bfloat16* aH = (z == 0) ? a0h : (z == 1) ? a1h : a2h;
    const __nv_bfloat16* aL = (z == 0) ? a0l : (z == 1) ? a1l : a2l;
    const __nv_bfloat16* bH = (z == 0) ? w0h : (z == 1) ? w1h : w2h;
    const __nv_bfloat16* bL = (z == 0) ? w0l : (z == 1) ? w1l : w2l;
    const float* bias = (z == 0) ? bias0 : (z == 1) ? bias1 : bias2;
    __nv_bfloat16* Chi = (z == 0) ? C0h : (z == 1) ? C1h : C2h;
    __nv_bfloat16* Clo = (z == 0) ? C0l : (z == 1) ? C1l : C2l;

    const int arow = tid >> 2, as4 = (tid & 3) * 8;

    float acc[2][8][4];
    #pragma unroll
    for (int mi = 0; mi < 2; mi++)
        #pragma unroll
        for (int nj = 0; nj < 8; nj++)
            #pragma unroll
            for (int q = 0; q < 4; q++) acc[mi][nj][q] = 0.0f;

    auto issue = [&](int c, int buf) {
        const int kk = c * BK;
        const uint32_t base = smb + buf * BUF;
        uint32_t aoff = (uint32_t)(arow * 40 + as4) * 2;
        cp16(base + aoff,       aH + (size_t)(bm + arow) * KDIM + kk + as4);
        cp16(base + A_T + aoff, aL + (size_t)(bm + arow) * KDIM + kk + as4);
        #pragma unroll
        for (int i = 0; i < 2; i++) {
            int idx = tid + i * 512;
            int br = idx >> 2, bs4 = (idx & 3) * 8;
            uint32_t boff = (uint32_t)(br * 40 + bs4) * 2;
            cp16(base + 2 * A_T + boff,       bH + (size_t)(bn + br) * KDIM + kk + bs4);
            cp16(base + 2 * A_T + B_T + boff, bL + (size_t)(bn + br) * KDIM + kk + bs4);
        }
        asm volatile("cp.async.commit_group;" ::: "memory");
    };

    auto compute = [&](int buf) {
        const uint32_t aBh = smb + buf * BUF;
        const uint32_t aBl = aBh + A_T;
        const uint32_t bBh = aBh + 2 * A_T;
        const uint32_t bBl = bBh + B_T;
        const int bmat = l >> 3, br8 = l & 7;
        #pragma unroll
        for (int ks = 0; ks < 2; ks++) {
            uint32_t ah[2][4], al[2][4];
            #pragma unroll
            for (int mi = 0; mi < 2; mi++) {
                uint32_t aoff = (uint32_t)((wm + mi * 16 + (l & 15)) * 40
                                           + ks * 16 + (l >> 4) * 8) * 2;
                ldmx4(ah[mi][0], ah[mi][1], ah[mi][2], ah[mi][3], aBh + aoff);
                ldmx4(al[mi][0], al[mi][1], al[mi][2], al[mi][3], aBl + aoff);
            }
            #pragma unroll
            for (int p = 0; p < 4; p++) {
                uint32_t boff = (uint32_t)((wn + p * 16 + ((bmat >> 1) << 3) + br8) * 40
                                           + ks * 16 + ((bmat & 1) << 3)) * 2;
                uint32_t bh0, bh1, bh2, bh3, bl0, bl1, bl2, bl3;
                ldmx4(bh0, bh1, bh2, bh3, bBh + boff);
                ldmx4(bl0, bl1, bl2, bl3, bBl + boff);
                #pragma unroll
                for (int mi = 0; mi < 2; mi++) {
                    mma16816(acc[mi][2 * p],     ah[mi], bh0, bh1);
                    mma16816(acc[mi][2 * p + 1], ah[mi], bh2, bh3);
                    mma16816(acc[mi][2 * p],     ah[mi], bl0, bl1);
                    mma16816(acc[mi][2 * p + 1], ah[mi], bl2, bl3);
                    mma16816(acc[mi][2 * p],     al[mi], bh0, bh1);
                    mma16816(acc[mi][2 * p + 1], al[mi], bh2, bh3);
                }
            }
        }
    };

    issue(0, 0);
    issue(1, 1);
    for (int c = 0; c < CHUNKS; ++c) {
        if (c + 1 < CHUNKS) {
            asm volatile("cp.async.wait_group 1;" ::: "memory");
        } else {
            asm volatile("cp.async.wait_group 0;" ::: "memory");
        }
        __syncthreads();
        compute(c % 3);
        __syncthreads();
        if (c + 2 < CHUNKS) issue(c + 2, (c + 2) % 3);
    }

    #pragma unroll
    for (int mi = 0; mi < 2; mi++) {
        int r0 = bm + wm + mi * 16 + (l >> 2);
        #pragma unroll
        for (int nj = 0; nj < 8; nj++) {
            int col = bn + wn + nj * 8 + (l & 3) * 2;
            float2 bv = *(const float2*)&bias[col];
            float v0 = acc[mi][nj][0] + bv.x;
            float v1 = acc[mi][nj][1] + bv.y;
            float v2 = acc[mi][nj][2] + bv.x;
            float v3 = acc[mi][nj][3] + bv.y;
            if (SPLIT) {
                uint32_t ph = cvt2bf(v1, v0);
                uint32_t pl = cvt2bf(v1 - bfhi(ph), v0 - bflo(ph));
                *(uint32_t*)&Chi[(size_t)r0 * D_ + col] = ph;
                *(uint32_t*)&Clo[(size_t)r0 * D_ + col] = pl;
                ph = cvt2bf(v3, v2);
                pl = cvt2bf(v3 - bfhi(ph), v2 - bflo(ph));
                *(uint32_t*)&Chi[(size_t)(r0 + 8) * D_ + col] = ph;
                *(uint32_t*)&Clo[(size_t)(r0 + 8) * D_ + col] = pl;
            } else {
                *(float2*)&Cf[(size_t)r0 * D_ + col] = make_float2(v0, v1);
                *(float2*)&Cf[(size_t)(r0 + 8) * D_ + col] = make_float2(v2, v3);
            }
        }
    }
}

// ===========================================================================
// Tensor-core flash attention (bf16 hi/lo, fp32 softmax) — round-4 version.
// ===========================================================================
__global__ __launch_bounds__(256) void attn_mma(
    const __nv_bfloat16* __restrict__ qHi, const __nv_bfloat16* __restrict__ qLo,
    const __nv_bfloat16* __restrict__ kHi, const __nv_bfloat16* __restrict__ kLo,
    const __nv_bfloat16* __restrict__ vHi, const __nv_bfloat16* __restrict__ vLo,
    const int* __restrict__ mask,
    __nv_bfloat16* __restrict__ cHi, __nv_bfloat16* __restrict__ cLo)
{
    extern __shared__ char dynsm[];
    const uint32_t smb = smem_u32(dynsm);
    const int tid = threadIdx.x;
    const int w = tid >> 5, l = tid & 31;
    const int b = blockIdx.z, h = blockIdx.y;
    const int q0 = blockIdx.x * 128;
    const size_t bS = (size_t)b * S_;
    const int hd = h * DK_;

    auto load_tile = [&](const __nv_bfloat16* g, uint32_t off, int tok0) {
        #pragma unroll
        for (int t = 0; t < 4; t++) {
            int idx = tid + t * 256;
            int row = idx >> 3, seg = (idx & 7) * 8;
            cp16(smb + off + (uint32_t)(row * SK + seg) * 2,
                 g + (bS + tok0 + row) * D_ + hd + seg);
        }
    };
    auto load_kv = [&](int kt, int buf) {
        int tok0 = kt * 128;
        load_tile(kHi, KV_OFF(buf, 0), tok0);
        load_tile(kLo, KV_OFF(buf, 1), tok0);
        load_tile(vHi, KV_OFF(buf, 2), tok0);
        load_tile(vLo, KV_OFF(buf, 3), tok0);
        if (tid < 128) cp4(smb + MS_OFF + (uint32_t)(buf * 128 + tid) * 4,
                           mask + b * S_ + tok0 + tid);
    };

    load_tile(qHi, QH_OFF, q0);
    load_tile(qLo, QL_OFF, q0);
    load_kv(0, 0);
    asm volatile("cp.async.commit_group;" ::: "memory");

    float Oacc[8][4];
    #pragma unroll
    for (int nf = 0; nf < 8; nf++)
        #pragma unroll
        for (int q = 0; q < 4; q++) Oacc[nf][q] = 0.0f;
    float mrun0 = -1e30f, mrun1 = -1e30f, lrun0 = 0.0f, lrun1 = 0.0f;

    const uint32_t a_off = (uint32_t)((w * 16 + (l & 15)) * SK + ((l >> 4) << 3)) * 2;
    const int bmat = l >> 3, br8 = l & 7;

    for (int kt = 0; kt < 16; kt++) {
        const int buf = kt & 1;
        if (kt < 15) {
            load_kv(kt + 1, buf ^ 1);
            asm volatile("cp.async.commit_group;" ::: "memory");
            asm volatile("cp.async.wait_group 1;" ::: "memory");
        } else {
            asm volatile("cp.async.wait_group 0;" ::: "memory");
        }
        __syncthreads();

        const uint32_t KhB = smb + KV_OFF(buf, 0), KlB = smb + KV_OFF(buf, 1);
        const uint32_t VhB = smb + KV_OFF(buf, 2), VlB = smb + KV_OFF(buf, 3);
        const int* ms = (const int*)(dynsm + MS_OFF + buf * 512);

        float sacc[16][4];
        #pragma unroll
        for (int f = 0; f < 16; f++)
            #pragma unroll
            for (int q = 0; q < 4; q++) sacc[f][q] = 0.0f;

        #pragma unroll
        for (int kc = 0; kc < 4; kc++) {
            uint32_t aH[4], aL[4];
            ldmx4(aH[0], aH[1], aH[2], aH[3], smb + QH_OFF + a_off + kc * 32);
            ldmx4(aL[0], aL[1], aL[2], aL[3], smb + QL_OFF + a_off + kc * 32);
            #pragma unroll
            for (int np = 0; np < 8; np++) {
                uint32_t badr = (uint32_t)((np * 16 + ((bmat >> 1) << 3) + br8) * SK
                                           + kc * 16 + ((bmat & 1) << 3)) * 2;
                uint32_t bh0, bh1, bh2, bh3, bl0, bl1, bl2, bl3;
                ldmx4(bh0, bh1, bh2, bh3, KhB + badr);
                ldmx4(bl0, bl1, bl2, bl3, KlB + badr);
                mma16816(sacc[2 * np],     aH, bh0, bh1);
                mma16816(sacc[2 * np + 1], aH, bh2, bh3);
                mma16816(sacc[2 * np],     aH, bl0, bl1);
                mma16816(sacc[2 * np + 1], aH, bl2, bl3);
                mma16816(sacc[2 * np],     aL, bh0, bh1);
                mma16816(sacc[2 * np + 1], aL, bh2, bh3);
            }
        }

        float mx0 = -1e30f, mx1 = -1e30f;
        #pragma unroll
        for (int f = 0; f < 16; f++) {
            int c0 = f * 8 + (l & 3) * 2;
            int mk0 = ms[c0], mk1 = ms[c0 + 1];
            float t0 = mk0 ? sacc[f][0] * 0.125f : -1e30f;
            float t1 = mk1 ? sacc[f][1] * 0.125f : -1e30f;
            float t2 = mk0 ? sacc[f][2] * 0.125f : -1e30f;
            float t3 = mk1 ? sacc[f][3] * 0.125f : -1e30f;
            sacc[f][0] = t0; sacc[f][1] = t1; sacc[f][2] = t2; sacc[f][3] = t3;
            mx0 = fmaxf(mx0, fmaxf(t0, t1));
            mx1 = fmaxf(mx1, fmaxf(t2, t3));
        }
        mx0 = fmaxf(mx0, __shfl_xor_sync(0xffffffffu, mx0, 1));
        mx0 = fmaxf(mx0, __shfl_xor_sync(0xffffffffu, mx0, 2));
        mx1 = fmaxf(mx1, __shfl_xor_sync(0xffffffffu, mx1, 1));
        mx1 = fmaxf(mx1, __shfl_xor_sync(0xffffffffu, mx1, 2));
        float mn0 = fmaxf(mrun0, mx0), mn1 = fmaxf(mrun1, mx1);
        float cor0 = __expf(mrun0 - mn0), cor1 = __expf(mrun1 - mn1);
        mrun0 = mn0; mrun1 = mn1;
        float sum0 = 0.0f, sum1 = 0.0f;
        #pragma unroll
        for (int f = 0; f < 16; f++) {
            float p0 = __expf(sacc[f][0] - mn0);
            float p1 = __expf(sacc[f][1] - mn0);
            float p2 = __expf(sacc[f][2] - mn1);
            float p3 = __expf(sacc[f][3] - mn1);
            sacc[f][0] = p0; sacc[f][1] = p1; sacc[f][2] = p2; sacc[f][3] = p3;
            sum0 += p0 + p1; sum1 += p2 + p3;
        }
        sum0 += __shfl_xor_sync(0xffffffffu, sum0, 1);
        sum0 += __shfl_xor_sync(0xffffffffu, sum0, 2);
        sum1 += __shfl_xor_sync(0xffffffffu, sum1, 1);
        sum1 += __shfl_xor_sync(0xffffffffu, sum1, 2);
        lrun0 = lrun0 * cor0 + sum0;
        lrun1 = lrun1 * cor1 + sum1;
        #pragma unroll
        for (int nf = 0; nf < 8; nf++) {
            Oacc[nf][0] *= cor0; Oacc[nf][1] *= cor0;
            Oacc[nf][2] *= cor1; Oacc[nf][3] *= cor1;
        }

        #pragma unroll
        for (int kc2 = 0; kc2 < 8; kc2++) {
            const float* f0 = sacc[2 * kc2];
            const float* f1 = sacc[2 * kc2 + 1];
            uint32_t aH2[4], aL2[4];
            aH2[0] = cvt2bf(f0[1], f0[0]);
            aH2[1] = cvt2bf(f0[3], f0[2]);
            aH2[2] = cvt2bf(f1[1], f1[0]);
            aH2[3] = cvt2bf(f1[3], f1[2]);
            aL2[0] = cvt2bf(f0[1] - bfhi(aH2[0]), f0[0] - bflo(aH2[0]));
            aL2[1] = cvt2bf(f0[3] - bfhi(aH2[1]), f0[2] - bflo(aH2[1]));
            aL2[2] = cvt2bf(f1[1] - bfhi(aH2[2]), f1[0] - bflo(aH2[2]));
            aL2[3] = cvt2bf(f1[3] - bfhi(aH2[3]), f1[2] - bflo(aH2[3]));
            #pragma unroll
            for (int nf = 0; nf < 4; nf++) {
                uint32_t vadr = (uint32_t)((kc2 * 16 + (l & 15)) * SK
                                           + nf * 16 + ((l >> 4) << 3)) * 2;
                uint32_t vh0, vh1, vh2, vh3, vl0, vl1, vl2, vl3;
                ldmx4t(vh0, vh1, vh2, vh3, VhB + vadr);
                ldmx4t(vl0, vl1, vl2, vl3, VlB + vadr);
                mma16816(Oacc[2 * nf],     aH2, vh0, vh1);
                mma16816(Oacc[2 * nf + 1], aH2, vh2, vh3);
                mma16816(Oacc[2 * nf],     aH2, vl0, vl1);
                mma16816(Oacc[2 * nf + 1], aH2, vl2, vl3);
                mma16816(Oacc[2 * nf],     aL2, vh0, vh1);
                mma16816(Oacc[2 * nf + 1], aL2, vh2, vh3);
            }
        }
        __syncthreads();
    }

    const float inv0 = 1.0f / lrun0;
    const float inv1 = 1.0f / lrun1;
    const int r0 = q0 + w * 16 + (l >> 2);
    #pragma unroll
    for (int nf = 0; nf < 8; nf++) {
        int col = hd + nf * 8 + (l & 3) * 2;
        float v0 = Oacc[nf][0] * inv0, v1 = Oacc[nf][1] * inv0;
        uint32_t ph = cvt2bf(v1, v0);
        uint32_t pl = cvt2bf(v1 - bfhi(ph), v0 - bflo(ph));
        *(uint32_t*)&cHi[(bS + r0) * D_ + col] = ph;
        *(uint32_t*)&cLo[(bS + r0) * D_ + col] = pl;
        float v2 = Oacc[nf][2] * inv1, v3 = Oacc[nf][3] * inv1;
        ph = cvt2bf(v3, v2);
        pl = cvt2bf(v3 - bfhi(ph), v2 - bflo(ph));
        *(uint32_t*)&cHi[(bS + r0 + 8) * D_ + col] = ph;
        *(uint32_t*)&cLo[(bS + r0 + 8) * D_ + col] = pl;
    }
}

// ---------------------------------------------------------------------------
extern "C" void kernel_launch(void* const* d_in, const int* in_sizes, int n_in,
                              void* d_out, int out_size)
{
    (void)in_sizes; (void)n_in; (void)out_size;
    const float* query = (const float*)d_in[0];
    const float* key   = (const float*)d_in[1];
    const float* value = (const float*)d_in[2];
    const int*   mask  = (const int*)d_in[3];
    const float* Wq = (const float*)d_in[4];
    const float* bq = (const float*)d_in[5];
    const float* Wk = (const float*)d_in[6];
    const float* bk = (const float*)d_in[7];
    const float* Wv = (const float*)d_in[8];
    const float* bv = (const float*)d_in[9];
    const float* Wo = (const float*)d_in[10];
    const float* bo = (const float*)d_in[11];
    float* out = (float*)d_out;

    __nv_bfloat16 *qh, *ql, *kh, *kl, *vh, *vl, *ch, *cl;
    __nv_bfloat16 *aqh, *aql, *akh, *akl, *avh, *avl;
    __nv_bfloat16 *wqh, *wql, *wkh, *wkl, *wvh, *wvl, *woh, *wol;
    cudaGetSymbolAddress((void**)&qh, g_qh);   cudaGetSymbolAddress((void**)&ql, g_ql);
    cudaGetSymbolAddress((void**)&kh, g_kh);   cudaGetSymbolAddress((void**)&kl, g_kl);
    cudaGetSymbolAddress((void**)&vh, g_vh);   cudaGetSymbolAddress((void**)&vl, g_vl);
    cudaGetSymbolAddress((void**)&ch, g_ch);   cudaGetSymbolAddress((void**)&cl, g_cl);
    cudaGetSymbolAddress((void**)&aqh, g_aqh); cudaGetSymbolAddress((void**)&aql, g_aql);
    cudaGetSymbolAddress((void**)&akh, g_akh); cudaGetSymbolAddress((void**)&akl, g_akl);
    cudaGetSymbolAddress((void**)&avh, g_avh); cudaGetSymbolAddress((void**)&avl, g_avl);
    cudaGetSymbolAddress((void**)&wqh, g_wqh); cudaGetSymbolAddress((void**)&wql, g_wql);
    cudaGetSymbolAddress((void**)&wkh, g_wkh); cudaGetSymbolAddress((void**)&wkl, g_wkl);
    cudaGetSymbolAddress((void**)&wvh, g_wvh); cudaGetSymbolAddress((void**)&wvl, g_wvl);
    cudaGetSymbolAddress((void**)&woh, g_woh); cudaGetSymbolAddress((void**)&wol, g_wol);

    const int actN4 = B_ * S_ * D_ / 4;   // 1048576
    const int wN4   = D_ * D_ / 4;        // 262144

    cudaFuncSetAttribute(gemm3<true>, cudaFuncAttributeMaxDynamicSharedMemorySize,
                         GEMM_SMEM);
    cudaFuncSetAttribute(gemm3<false>, cudaFuncAttributeMaxDynamicSharedMemorySize,
                         GEMM_SMEM);
    cudaFuncSetAttribute(attn_mma, cudaFuncAttributeMaxDynamicSharedMemorySize,
                         ATTN_SMEM);

    // Splits (2 batched launches)
    split_acts<<<dim3(actN4 / 256, 3), 256>>>(query, key, value,
                                              aqh, aql, akh, akl, avh, avl);
    split_weights<<<dim3(wN4 / 256, 4), 256>>>(Wq, Wk, Wv, Wo,
                                               wqh, wql, wkh, wkl,
                                               wvh, wvl, woh, wol);

    // Fused Q/K/V projections (one launch, grid.z = 3)
    dim3 ggrid(D_ / BN, (B_ * S_) / BM, 3);
    gemm3<true><<<ggrid, 512, GEMM_SMEM>>>(
        aqh, aql, wqh, wql, bq,
        akh, akl, wkh, wkl, bk,
        avh, avl, wvh, wvl, bv,
        nullptr, qh, ql, kh, kl, vh, vl);

    // Attention
    dim3 agrid(S_ / 128, H_, B_);
    attn_mma<<<agrid, 256, ATTN_SMEM>>>(qh, ql, kh, kl, vh, vl, mask, ch, cl);

    // Output projection (fp32 out)
    dim3 ogrid(D_ / BN, (B_ * S_) / BM, 1);
    gemm3<false><<<ogrid, 512, GEMM_SMEM>>>(
        ch, cl, woh, wol, bo,
        ch, cl, woh, wol, bo,
        ch, cl, woh, wol, bo,
        out, nullptr, nullptr, nullptr, nullptr, nullptr, nullptr);
}

// round 6
// speedup vs baseline: 2.7427x; 1.0510x over previous
#include <cuda_runtime.h>
#include <cuda_bf16.h>
#include <math.h>
#include <stdint.h>

// Problem constants
#define B_  2
#define S_  2048
#define D_  1024
#define H_  16
#define DK_ 64

// GEMM tiling
#define BM 128
#define BN 256
#define BK 32
#define KDIM 1024
#define CHUNKS 32
#define A_T 10240            // 128 x 40 x 2B
#define B_T 20480            // 256 x 40 x 2B
#define BUF (2 * A_T + 2 * B_T)          // 61440
#define GEMM_SMEM (3 * BUF)              // 184320

// Attention smem layout (64-key tiles, 2 CTAs/SM)
#define SK 72
#define QT_B (128 * SK * 2)              // 18432
#define KT_B (64 * SK * 2)               // 9216
#define QH_OFF 0
#define QL_OFF QT_B
#define KV_OFF(buf, t) (2 * QT_B + (buf) * 4 * KT_B + (t) * KT_B)
#define MS_OFF (2 * QT_B + 8 * KT_B)     // 110592
#define ATTN_SMEM (MS_OFF + 512)         // 111104

// Scratch (device globals)
__device__ __nv_bfloat16 g_qh[B_*S_*D_], g_ql[B_*S_*D_];
__device__ __nv_bfloat16 g_kh[B_*S_*D_], g_kl[B_*S_*D_];
__device__ __nv_bfloat16 g_vh[B_*S_*D_], g_vl[B_*S_*D_];
__device__ __nv_bfloat16 g_ch[B_*S_*D_], g_cl[B_*S_*D_];
__device__ __nv_bfloat16 g_aqh[B_*S_*D_], g_aql[B_*S_*D_];
__device__ __nv_bfloat16 g_akh[B_*S_*D_], g_akl[B_*S_*D_];
__device__ __nv_bfloat16 g_avh[B_*S_*D_], g_avl[B_*S_*D_];
__device__ __nv_bfloat16 g_wqh[D_*D_], g_wql[D_*D_];
__device__ __nv_bfloat16 g_wkh[D_*D_], g_wkl[D_*D_];
__device__ __nv_bfloat16 g_wvh[D_*D_], g_wvl[D_*D_];
__device__ __nv_bfloat16 g_woh[D_*D_], g_wol[D_*D_];

// ===========================================================================
// Helpers
// ===========================================================================
__device__ __forceinline__ uint32_t smem_u32(const void* p) {
    uint32_t a;
    asm("{ .reg .u64 t; cvta.to.shared.u64 t, %1; cvt.u32.u64 %0, t; }"
        : "=r"(a) : "l"(p));
    return a;
}
__device__ __forceinline__ void cp16(uint32_t dst, const void* src) {
    asm volatile("cp.async.cg.shared.global [%0], [%1], 16;" :: "r"(dst), "l"(src));
}
__device__ __forceinline__ void cp4(uint32_t dst, const void* src) {
    asm volatile("cp.async.ca.shared.global [%0], [%1], 4;" :: "r"(dst), "l"(src));
}
__device__ __forceinline__ void ldmx4(uint32_t& r0, uint32_t& r1,
                                      uint32_t& r2, uint32_t& r3, uint32_t addr) {
    asm volatile("ldmatrix.sync.aligned.m8n8.x4.shared.b16 {%0,%1,%2,%3}, [%4];"
                 : "=r"(r0), "=r"(r1), "=r"(r2), "=r"(r3) : "r"(addr));
}
__device__ __forceinline__ void ldmx4t(uint32_t& r0, uint32_t& r1,
                                       uint32_t& r2, uint32_t& r3, uint32_t addr) {
    asm volatile("ldmatrix.sync.aligned.m8n8.x4.trans.shared.b16 {%0,%1,%2,%3}, [%4];"
                 : "=r"(r0), "=r"(r1), "=r"(r2), "=r"(r3) : "r"(addr));
}
__device__ __forceinline__ void mma16816(float* c, const uint32_t* a,
                                         uint32_t b0, uint32_t b1) {
    asm volatile(
        "mma.sync.aligned.m16n8k16.row.col.f32.bf16.bf16.f32 "
        "{%0,%1,%2,%3}, {%4,%5,%6,%7}, {%8,%9}, {%0,%1,%2,%3};"
        : "+f"(c[0]), "+f"(c[1]), "+f"(c[2]), "+f"(c[3])
        : "r"(a[0]), "r"(a[1]), "r"(a[2]), "r"(a[3]), "r"(b0), "r"(b1));
}
__device__ __forceinline__ uint32_t pack2(unsigned short a, unsigned short b) {
    return (uint32_t)a | ((uint32_t)b << 16);
}
__device__ __forceinline__ uint32_t cvt2bf(float hi_elem, float lo_elem) {
    uint32_t r;
    asm("cvt.rn.bf16x2.f32 %0, %1, %2;" : "=r"(r) : "f"(hi_elem), "f"(lo_elem));
    return r;
}
__device__ __forceinline__ float bflo(uint32_t p) { return __uint_as_float(p << 16); }
__device__ __forceinline__ float bfhi(uint32_t p) { return __uint_as_float(p & 0xFFFF0000u); }

// ===========================================================================
// Split kernels (batched)
// ===========================================================================
__device__ __forceinline__ void split_one(const float* x, __nv_bfloat16* hi,
                                          __nv_bfloat16* lo, int i) {
    float4 v = ((const float4*)x)[i];
    float f[4] = {v.x, v.y, v.z, v.w};
    unsigned short h[4], l[4];
    #pragma unroll
    for (int j = 0; j < 4; j++) {
        __nv_bfloat16 bh = __float2bfloat16(f[j]);
        float r = f[j] - __bfloat162float(bh);
        h[j] = __bfloat16_as_ushort(bh);
        l[j] = __bfloat16_as_ushort(__float2bfloat16(r));
    }
    ((uint2*)hi)[i] = make_uint2(pack2(h[0], h[1]), pack2(h[2], h[3]));
    ((uint2*)lo)[i] = make_uint2(pack2(l[0], l[1]), pack2(l[2], l[3]));
}

__global__ __launch_bounds__(256) void split_acts(
    const float* __restrict__ q, const float* __restrict__ k, const float* __restrict__ v,
    __nv_bfloat16* qh, __nv_bfloat16* ql, __nv_bfloat16* kh, __nv_bfloat16* kl,
    __nv_bfloat16* vh, __nv_bfloat16* vl)
{
    int i = blockIdx.x * 256 + threadIdx.x;
    int z = blockIdx.y;
    const float* x = (z == 0) ? q : (z == 1) ? k : v;
    __nv_bfloat16* hi = (z == 0) ? qh : (z == 1) ? kh : vh;
    __nv_bfloat16* lo = (z == 0) ? ql : (z == 1) ? kl : vl;
    split_one(x, hi, lo, i);
}

__global__ __launch_bounds__(256) void split_weights(
    const float* __restrict__ w0, const float* __restrict__ w1,
    const float* __restrict__ w2, const float* __restrict__ w3,
    __nv_bfloat16* h0, __nv_bfloat16* l0, __nv_bfloat16* h1, __nv_bfloat16* l1,
    __nv_bfloat16* h2, __nv_bfloat16* l2, __nv_bfloat16* h3, __nv_bfloat16* l3)
{
    int i = blockIdx.x * 256 + threadIdx.x;
    int z = blockIdx.y;
    const float* x = (z == 0) ? w0 : (z == 1) ? w1 : (z == 2) ? w2 : w3;
    __nv_bfloat16* hi = (z == 0) ? h0 : (z == 1) ? h1 : (z == 2) ? h2 : h3;
    __nv_bfloat16* lo = (z == 0) ? l0 : (z == 1) ? l1 : (z == 2) ? l2 : l3;
    split_one(x, hi, lo, i);
}

// ===========================================================================
// GEMM (NT + bias), 3-product hi/lo per K-chunk, 3-stage cp.async, z-batched.
// ===========================================================================
template<bool SPLIT>
__global__ __launch_bounds__(512) void gemm3(
    const __nv_bfloat16* __restrict__ a0h, const __nv_bfloat16* __restrict__ a0l,
    const __nv_bfloat16* __restrict__ w0h, const __nv_bfloat16* __restrict__ w0l,
    const float* __restrict__ bias0,
    const __nv_bfloat16* __restrict__ a1h, const __nv_bfloat16* __restrict__ a1l,
    const __nv_bfloat16* __restrict__ w1h, const __nv_bfloat16* __restrict__ w1l,
    const float* __restrict__ bias1,
    const __nv_bfloat16* __restrict__ a2h, const __nv_bfloat16* __restrict__ a2l,
    const __nv_bfloat16* __restrict__ w2h, const __nv_bfloat16* __restrict__ w2l,
    const float* __restrict__ bias2,
    float* __restrict__ Cf,
    __nv_bfloat16* __restrict__ C0h, __nv_bfloat16* __restrict__ C0l,
    __nv_bfloat16* __restrict__ C1h, __nv_bfloat16* __restrict__ C1l,
    __nv_bfloat16* __restrict__ C2h, __nv_bfloat16* __restrict__ C2l)
{
    extern __shared__ char dynsm[];
    const uint32_t smb = smem_u32(dynsm);
    const int tid = threadIdx.x;
    const int l = tid & 31;
    const int wid = tid >> 5;
    const int wm = (wid & 3) * 32;
    const int wn = (wid >> 2) * 64;
    const int bm = blockIdx.y * BM;
    const int bn = blockIdx.x * BN;
    const int z = blockIdx.z;

    const __nv_bfloat16* aH = (z == 0) ? a0h : (z == 1) ? a1h : a2h;
    const __nv_bfloat16* aL = (z == 0) ? a0l : (z == 1) ? a1l : a2l;
    const __nv_bfloat16* bH = (z == 0) ? w0h : (z == 1) ? w1h : w2h;
    const __nv_bfloat16* bL = (z == 0) ? w0l : (z == 1) ? w1l : w2l;
    const float* bias = (z == 0) ? bias0 : (z == 1) ? bias1 : bias2;
    __nv_bfloat16* Chi = (z == 0) ? C0h : (z == 1) ? C1h : C2h;
    __nv_bfloat16* Clo = (z == 0) ? C0l : (z == 1) ? C1l : C2l;

    const int arow = tid >> 2, as4 = (tid & 3) * 8;

    float acc[2][8][4];
    #pragma unroll
    for (int mi = 0; mi < 2; mi++)
        #pragma unroll
        for (int nj = 0; nj < 8; nj++)
            #pragma unroll
            for (int q = 0; q < 4; q++) acc[mi][nj][q] = 0.0f;

    auto issue = [&](int c, int buf) {
        const int kk = c * BK;
        const uint32_t base = smb + buf * BUF;
        uint32_t aoff = (uint32_t)(arow * 40 + as4) * 2;
        cp16(base + aoff,       aH + (size_t)(bm + arow) * KDIM + kk + as4);
        cp16(base + A_T + aoff, aL + (size_t)(bm + arow) * KDIM + kk + as4);
        #pragma unroll
        for (int i = 0; i < 2; i++) {
            int idx = tid + i * 512;
            int br = idx >> 2, bs4 = (idx & 3) * 8;
            uint32_t boff = (uint32_t)(br * 40 + bs4) * 2;
            cp16(base + 2 * A_T + boff,       bH + (size_t)(bn + br) * KDIM + kk + bs4);
            cp16(base + 2 * A_T + B_T + boff, bL + (size_t)(bn + br) * KDIM + kk + bs4);
        }
        asm volatile("cp.async.commit_group;" ::: "memory");
    };

    auto compute = [&](int buf) {
        const uint32_t aBh = smb + buf * BUF;
        const uint32_t aBl = aBh + A_T;
        const uint32_t bBh = aBh + 2 * A_T;
        const uint32_t bBl = bBh + B_T;
        const int bmat = l >> 3, br8 = l & 7;
        #pragma unroll
        for (int ks = 0; ks < 2; ks++) {
            uint32_t ah[2][4], al[2][4];
            #pragma unroll
            for (int mi = 0; mi < 2; mi++) {
                uint32_t aoff = (uint32_t)((wm + mi * 16 + (l & 15)) * 40
                                           + ks * 16 + (l >> 4) * 8) * 2;
                ldmx4(ah[mi][0], ah[mi][1], ah[mi][2], ah[mi][3], aBh + aoff);
                ldmx4(al[mi][0], al[mi][1], al[mi][2], al[mi][3], aBl + aoff);
            }
            #pragma unroll
            for (int p = 0; p < 4; p++) {
                uint32_t boff = (uint32_t)((wn + p * 16 + ((bmat >> 1) << 3) + br8) * 40
                                           + ks * 16 + ((bmat & 1) << 3)) * 2;
                uint32_t bh0, bh1, bh2, bh3, bl0, bl1, bl2, bl3;
                ldmx4(bh0, bh1, bh2, bh3, bBh + boff);
                ldmx4(bl0, bl1, bl2, bl3, bBl + boff);
                #pragma unroll
                for (int mi = 0; mi < 2; mi++) {
                    mma16816(acc[mi][2 * p],     ah[mi], bh0, bh1);
                    mma16816(acc[mi][2 * p + 1], ah[mi], bh2, bh3);
                    mma16816(acc[mi][2 * p],     ah[mi], bl0, bl1);
                    mma16816(acc[mi][2 * p + 1], ah[mi], bl2, bl3);
                    mma16816(acc[mi][2 * p],     al[mi], bh0, bh1);
                    mma16816(acc[mi][2 * p + 1], al[mi], bh2, bh3);
                }
            }
        }
    };

    issue(0, 0);
    issue(1, 1);
    for (int c = 0; c < CHUNKS; ++c) {
        if (c + 1 < CHUNKS) {
            asm volatile("cp.async.wait_group 1;" ::: "memory");
        } else {
            asm volatile("cp.async.wait_group 0;" ::: "memory");
        }
        __syncthreads();
        compute(c % 3);
        __syncthreads();
        if (c + 2 < CHUNKS) issue(c + 2, (c + 2) % 3);
    }

    #pragma unroll
    for (int mi = 0; mi < 2; mi++) {
        int r0 = bm + wm + mi * 16 + (l >> 2);
        #pragma unroll
        for (int nj = 0; nj < 8; nj++) {
            int col = bn + wn + nj * 8 + (l & 3) * 2;
            float2 bv = *(const float2*)&bias[col];
            float v0 = acc[mi][nj][0] + bv.x;
            float v1 = acc[mi][nj][1] + bv.y;
            float v2 = acc[mi][nj][2] + bv.x;
            float v3 = acc[mi][nj][3] + bv.y;
            if (SPLIT) {
                uint32_t ph = cvt2bf(v1, v0);
                uint32_t pl = cvt2bf(v1 - bfhi(ph), v0 - bflo(ph));
                *(uint32_t*)&Chi[(size_t)r0 * D_ + col] = ph;
                *(uint32_t*)&Clo[(size_t)r0 * D_ + col] = pl;
                ph = cvt2bf(v3, v2);
                pl = cvt2bf(v3 - bfhi(ph), v2 - bflo(ph));
                *(uint32_t*)&Chi[(size_t)(r0 + 8) * D_ + col] = ph;
                *(uint32_t*)&Clo[(size_t)(r0 + 8) * D_ + col] = pl;
            } else {
                *(float2*)&Cf[(size_t)r0 * D_ + col] = make_float2(v0, v1);
                *(float2*)&Cf[(size_t)(r0 + 8) * D_ + col] = make_float2(v2, v3);
            }
        }
    }
}

// ===========================================================================
// Tensor-core flash attention (bf16 hi/lo, fp32 softmax).
// 64-key tiles, 108.5 KB smem, 2 CTAs/SM target.
// ===========================================================================
__global__ __launch_bounds__(256, 2) void attn_mma(
    const __nv_bfloat16* __restrict__ qHi, const __nv_bfloat16* __restrict__ qLo,
    const __nv_bfloat16* __restrict__ kHi, const __nv_bfloat16* __restrict__ kLo,
    const __nv_bfloat16* __restrict__ vHi, const __nv_bfloat16* __restrict__ vLo,
    const int* __restrict__ mask,
    __nv_bfloat16* __restrict__ cHi, __nv_bfloat16* __restrict__ cLo)
{
    extern __shared__ char dynsm[];
    const uint32_t smb = smem_u32(dynsm);
    const int tid = threadIdx.x;
    const int w = tid >> 5, l = tid & 31;
    const int b = blockIdx.z, h = blockIdx.y;
    const int q0 = blockIdx.x * 128;
    const size_t bS = (size_t)b * S_;
    const int hd = h * DK_;

    auto load_q = [&](const __nv_bfloat16* g, uint32_t off) {
        #pragma unroll
        for (int t = 0; t < 4; t++) {
            int idx = tid + t * 256;
            int row = idx >> 3, seg = (idx & 7) * 8;
            cp16(smb + off + (uint32_t)(row * SK + seg) * 2,
                 g + (bS + q0 + row) * D_ + hd + seg);
        }
    };
    auto load_kv_tile = [&](const __nv_bfloat16* g, uint32_t off, int tok0) {
        #pragma unroll
        for (int t = 0; t < 2; t++) {
            int idx = tid + t * 256;
            int row = idx >> 3, seg = (idx & 7) * 8;
            cp16(smb + off + (uint32_t)(row * SK + seg) * 2,
                 g + (bS + tok0 + row) * D_ + hd + seg);
        }
    };
    auto load_kv = [&](int kt, int buf) {
        int tok0 = kt * 64;
        load_kv_tile(kHi, KV_OFF(buf, 0), tok0);
        load_kv_tile(kLo, KV_OFF(buf, 1), tok0);
        load_kv_tile(vHi, KV_OFF(buf, 2), tok0);
        load_kv_tile(vLo, KV_OFF(buf, 3), tok0);
        if (tid < 64) cp4(smb + MS_OFF + (uint32_t)(buf * 64 + tid) * 4,
                          mask + b * S_ + tok0 + tid);
    };

    load_q(qHi, QH_OFF);
    load_q(qLo, QL_OFF);
    load_kv(0, 0);
    asm volatile("cp.async.commit_group;" ::: "memory");

    float Oacc[8][4];
    #pragma unroll
    for (int nf = 0; nf < 8; nf++)
        #pragma unroll
        for (int q = 0; q < 4; q++) Oacc[nf][q] = 0.0f;
    float mrun0 = -1e30f, mrun1 = -1e30f, lrun0 = 0.0f, lrun1 = 0.0f;

    const uint32_t a_off = (uint32_t)((w * 16 + (l & 15)) * SK + ((l >> 4) << 3)) * 2;
    const int bmat = l >> 3, br8 = l & 7;

    for (int kt = 0; kt < 32; kt++) {
        const int buf = kt & 1;
        if (kt < 31) {
            load_kv(kt + 1, buf ^ 1);
            asm volatile("cp.async.commit_group;" ::: "memory");
            asm volatile("cp.async.wait_group 1;" ::: "memory");
        } else {
            asm volatile("cp.async.wait_group 0;" ::: "memory");
        }
        __syncthreads();

        const uint32_t KhB = smb + KV_OFF(buf, 0), KlB = smb + KV_OFF(buf, 1);
        const uint32_t VhB = smb + KV_OFF(buf, 2), VlB = smb + KV_OFF(buf, 3);
        const int* ms = (const int*)(dynsm + MS_OFF + buf * 256);

        float sacc[8][4];
        #pragma unroll
        for (int f = 0; f < 8; f++)
            #pragma unroll
            for (int q = 0; q < 4; q++) sacc[f][q] = 0.0f;

        // ---- S = Q K^T (3-pass hi/lo) ----
        #pragma unroll
        for (int kc = 0; kc < 4; kc++) {
            uint32_t aH[4], aL[4];
            ldmx4(aH[0], aH[1], aH[2], aH[3], smb + QH_OFF + a_off + kc * 32);
            ldmx4(aL[0], aL[1], aL[2], aL[3], smb + QL_OFF + a_off + kc * 32);
            #pragma unroll
            for (int np = 0; np < 4; np++) {
                uint32_t badr = (uint32_t)((np * 16 + ((bmat >> 1) << 3) + br8) * SK
                                           + kc * 16 + ((bmat & 1) << 3)) * 2;
                uint32_t bh0, bh1, bh2, bh3, bl0, bl1, bl2, bl3;
                ldmx4(bh0, bh1, bh2, bh3, KhB + badr);
                ldmx4(bl0, bl1, bl2, bl3, KlB + badr);
                mma16816(sacc[2 * np],     aH, bh0, bh1);
                mma16816(sacc[2 * np + 1], aH, bh2, bh3);
                mma16816(sacc[2 * np],     aH, bl0, bl1);
                mma16816(sacc[2 * np + 1], aH, bl2, bl3);
                mma16816(sacc[2 * np],     aL, bh0, bh1);
                mma16816(sacc[2 * np + 1], aL, bh2, bh3);
            }
        }

        // ---- scale + mask + online softmax ----
        float mx0 = -1e30f, mx1 = -1e30f;
        #pragma unroll
        for (int f = 0; f < 8; f++) {
            int c0 = f * 8 + (l & 3) * 2;
            int mk0 = ms[c0], mk1 = ms[c0 + 1];
            float t0 = mk0 ? sacc[f][0] * 0.125f : -1e30f;
            float t1 = mk1 ? sacc[f][1] * 0.125f : -1e30f;
            float t2 = mk0 ? sacc[f][2] * 0.125f : -1e30f;
            float t3 = mk1 ? sacc[f][3] * 0.125f : -1e30f;
            sacc[f][0] = t0; sacc[f][1] = t1; sacc[f][2] = t2; sacc[f][3] = t3;
            mx0 = fmaxf(mx0, fmaxf(t0, t1));
            mx1 = fmaxf(mx1, fmaxf(t2, t3));
        }
        mx0 = fmaxf(mx0, __shfl_xor_sync(0xffffffffu, mx0, 1));
        mx0 = fmaxf(mx0, __shfl_xor_sync(0xffffffffu, mx0, 2));
        mx1 = fmaxf(mx1, __shfl_xor_sync(0xffffffffu, mx1, 1));
        mx1 = fmaxf(mx1, __shfl_xor_sync(0xffffffffu, mx1, 2));
        float mn0 = fmaxf(mrun0, mx0), mn1 = fmaxf(mrun1, mx1);
        float cor0 = __expf(mrun0 - mn0), cor1 = __expf(mrun1 - mn1);
        mrun0 = mn0; mrun1 = mn1;
        float sum0 = 0.0f, sum1 = 0.0f;
        #pragma unroll
        for (int f = 0; f < 8; f++) {
            float p0 = __expf(sacc[f][0] - mn0);
            float p1 = __expf(sacc[f][1] - mn0);
            float p2 = __expf(sacc[f][2] - mn1);
            float p3 = __expf(sacc[f][3] - mn1);
            sacc[f][0] = p0; sacc[f][1] = p1; sacc[f][2] = p2; sacc[f][3] = p3;
            sum0 += p0 + p1; sum1 += p2 + p3;
        }
        sum0 += __shfl_xor_sync(0xffffffffu, sum0, 1);
        sum0 += __shfl_xor_sync(0xffffffffu, sum0, 2);
        sum1 += __shfl_xor_sync(0xffffffffu, sum1, 1);
        sum1 += __shfl_xor_sync(0xffffffffu, sum1, 2);
        lrun0 = lrun0 * cor0 + sum0;
        lrun1 = lrun1 * cor1 + sum1;
        #pragma unroll
        for (int nf = 0; nf < 8; nf++) {
            Oacc[nf][0] *= cor0; Oacc[nf][1] *= cor0;
            Oacc[nf][2] *= cor1; Oacc[nf][3] *= cor1;
        }

        // ---- O += P V (3-pass hi/lo) ----
        #pragma unroll
        for (int kc2 = 0; kc2 < 4; kc2++) {
            const float* f0 = sacc[2 * kc2];
            const float* f1 = sacc[2 * kc2 + 1];
            uint32_t aH2[4], aL2[4];
            aH2[0] = cvt2bf(f0[1], f0[0]);
            aH2[1] = cvt2bf(f0[3], f0[2]);
            aH2[2] = cvt2bf(f1[1], f1[0]);
            aH2[3] = cvt2bf(f1[3], f1[2]);
            aL2[0] = cvt2bf(f0[1] - bfhi(aH2[0]), f0[0] - bflo(aH2[0]));
            aL2[1] = cvt2bf(f0[3] - bfhi(aH2[1]), f0[2] - bflo(aH2[1]));
            aL2[2] = cvt2bf(f1[1] - bfhi(aH2[2]), f1[0] - bflo(aH2[2]));
            aL2[3] = cvt2bf(f1[3] - bfhi(aH2[3]), f1[2] - bflo(aH2[3]));
            #pragma unroll
            for (int nf = 0; nf < 4; nf++) {
                uint32_t vadr = (uint32_t)((kc2 * 16 + (l & 15)) * SK
                                           + nf * 16 + ((l >> 4) << 3)) * 2;
                uint32_t vh0, vh1, vh2, vh3, vl0, vl1, vl2, vl3;
                ldmx4t(vh0, vh1, vh2, vh3, VhB + vadr);
                ldmx4t(vl0, vl1, vl2, vl3, VlB + vadr);
                mma16816(Oacc[2 * nf],     aH2, vh0, vh1);
                mma16816(Oacc[2 * nf + 1], aH2, vh2, vh3);
                mma16816(Oacc[2 * nf],     aH2, vl0, vl1);
                mma16816(Oacc[2 * nf + 1], aH2, vl2, vl3);
                mma16816(Oacc[2 * nf],     aL2, vh0, vh1);
                mma16816(Oacc[2 * nf + 1], aL2, vh2, vh3);
            }
        }
        __syncthreads();
    }

    const float inv0 = 1.0f / lrun0;
    const float inv1 = 1.0f / lrun1;
    const int r0 = q0 + w * 16 + (l >> 2);
    #pragma unroll
    for (int nf = 0; nf < 8; nf++) {
        int col = hd + nf * 8 + (l & 3) * 2;
        float v0 = Oacc[nf][0] * inv0, v1 = Oacc[nf][1] * inv0;
        uint32_t ph = cvt2bf(v1, v0);
        uint32_t pl = cvt2bf(v1 - bfhi(ph), v0 - bflo(ph));
        *(uint32_t*)&cHi[(bS + r0) * D_ + col] = ph;
        *(uint32_t*)&cLo[(bS + r0) * D_ + col] = pl;
        float v2 = Oacc[nf][2] * inv1, v3 = Oacc[nf][3] * inv1;
        ph = cvt2bf(v3, v2);
        pl = cvt2bf(v3 - bfhi(ph), v2 - bflo(ph));
        *(uint32_t*)&cHi[(bS + r0 + 8) * D_ + col] = ph;
        *(uint32_t*)&cLo[(bS + r0 + 8) * D_ + col] = pl;
    }
}

// ---------------------------------------------------------------------------
extern "C" void kernel_launch(void* const* d_in, const int* in_sizes, int n_in,
                              void* d_out, int out_size)
{
    (void)in_sizes; (void)n_in; (void)out_size;
    const float* query = (const float*)d_in[0];
    const float* key   = (const float*)d_in[1];
    const float* value = (const float*)d_in[2];
    const int*   mask  = (const int*)d_in[3];
    const float* Wq = (const float*)d_in[4];
    const float* bq = (const float*)d_in[5];
    const float* Wk = (const float*)d_in[6];
    const float* bk = (const float*)d_in[7];
    const float* Wv = (const float*)d_in[8];
    const float* bv = (const float*)d_in[9];
    const float* Wo = (const float*)d_in[10];
    const float* bo = (const float*)d_in[11];
    float* out = (float*)d_out;

    __nv_bfloat16 *qh, *ql, *kh, *kl, *vh, *vl, *ch, *cl;
    __nv_bfloat16 *aqh, *aql, *akh, *akl, *avh, *avl;
    __nv_bfloat16 *wqh, *wql, *wkh, *wkl, *wvh, *wvl, *woh, *wol;
    cudaGetSymbolAddress((void**)&qh, g_qh);   cudaGetSymbolAddress((void**)&ql, g_ql);
    cudaGetSymbolAddress((void**)&kh, g_kh);   cudaGetSymbolAddress((void**)&kl, g_kl);
    cudaGetSymbolAddress((void**)&vh, g_vh);   cudaGetSymbolAddress((void**)&vl, g_vl);
    cudaGetSymbolAddress((void**)&ch, g_ch);   cudaGetSymbolAddress((void**)&cl, g_cl);
    cudaGetSymbolAddress((void**)&aqh, g_aqh); cudaGetSymbolAddress((void**)&aql, g_aql);
    cudaGetSymbolAddress((void**)&akh, g_akh); cudaGetSymbolAddress((void**)&akl, g_akl);
    cudaGetSymbolAddress((void**)&avh, g_avh); cudaGetSymbolAddress((void**)&avl, g_avl);
    cudaGetSymbolAddress((void**)&wqh, g_wqh); cudaGetSymbolAddress((void**)&wql, g_wql);
    cudaGetSymbolAddress((void**)&wkh, g_wkh); cudaGetSymbolAddress((void**)&wkl, g_wkl);
    cudaGetSymbolAddress((void**)&wvh, g_wvh); cudaGetSymbolAddress((void**)&wvl, g_wvl);
    cudaGetSymbolAddress((void**)&woh, g_woh); cudaGetSymbolAddress((void**)&wol, g_wol);

    const int actN4 = B_ * S_ * D_ / 4;   // 1048576
    const int wN4   = D_ * D_ / 4;        // 262144

    cudaFuncSetAttribute(gemm3<true>, cudaFuncAttributeMaxDynamicSharedMemorySize,
                         GEMM_SMEM);
    cudaFuncSetAttribute(gemm3<false>, cudaFuncAttributeMaxDynamicSharedMemorySize,
                         GEMM_SMEM);
    cudaFuncSetAttribute(attn_mma, cudaFuncAttributeMaxDynamicSharedMemorySize,
                         ATTN_SMEM);

    // Splits (2 batched launches)
    split_acts<<<dim3(actN4 / 256, 3), 256>>>(query, key, value,
                                              aqh, aql, akh, akl, avh, avl);
    split_weights<<<dim3(wN4 / 256, 4), 256>>>(Wq, Wk, Wv, Wo,
                                               wqh, wql, wkh, wkl,
                                               wvh, wvl, woh, wol);

    // Fused Q/K/V projections (one launch, grid.z = 3)
    dim3 ggrid(D_ / BN, (B_ * S_) / BM, 3);
    gemm3<true><<<ggrid, 512, GEMM_SMEM>>>(
        aqh, aql, wqh, wql, bq,
        akh, akl, wkh, wkl, bk,
        avh, avl, wvh, wvl, bv,
        nullptr, qh, ql, kh, kl, vh, vl);

    // Attention
    dim3 agrid(S_ / 128, H_, B_);
    attn_mma<<<agrid, 256, ATTN_SMEM>>>(qh, ql, kh, kl, vh, vl, mask, ch, cl);

    // Output projection (fp32 out)
    dim3 ogrid(D_ / BN, (B_ * S_) / BM, 1);
    gemm3<false><<<ogrid, 512, GEMM_SMEM>>>(
        ch, cl, woh, wol, bo,
        ch, cl, woh, wol, bo,
        ch, cl, woh, wol, bo,
        out, nullptr, nullptr, nullptr, nullptr, nullptr, nullptr);
}

// round 7
// speedup vs baseline: 2.8659x; 1.0449x over previous
#include <cuda_runtime.h>
#include <cuda_bf16.h>
#include <math.h>
#include <stdint.h>

// Problem constants
#define B_  2
#define S_  2048
#define D_  1024
#define H_  16
#define DK_ 64

// GEMM tiling: 128x128 tile, 256 threads, 2-stage, 2 CTAs/SM
#define BM 128
#define BN 128
#define BK 32
#define KDIM 1024
#define CHUNKS 32
#define A_T 10240            // 128 x 40 x 2B
#define B_T 10240            // 128 x 40 x 2B
#define BUF (2 * A_T + 2 * B_T)          // 40960
#define GEMM_SMEM (2 * BUF)              // 81920

// Attention smem layout (64-key tiles, 2 CTAs/SM)
#define SK 72
#define QT_B (128 * SK * 2)              // 18432
#define KT_B (64 * SK * 2)               // 9216
#define QH_OFF 0
#define QL_OFF QT_B
#define KV_OFF(buf, t) (2 * QT_B + (buf) * 4 * KT_B + (t) * KT_B)
#define MS_OFF (2 * QT_B + 8 * KT_B)     // 110592
#define ATTN_SMEM (MS_OFF + 512)         // 111104

// Scratch (device globals)
__device__ __nv_bfloat16 g_qh[B_*S_*D_], g_ql[B_*S_*D_];
__device__ __nv_bfloat16 g_kh[B_*S_*D_], g_kl[B_*S_*D_];
__device__ __nv_bfloat16 g_vh[B_*S_*D_], g_vl[B_*S_*D_];
__device__ __nv_bfloat16 g_ch[B_*S_*D_], g_cl[B_*S_*D_];
__device__ __nv_bfloat16 g_aqh[B_*S_*D_], g_aql[B_*S_*D_];
__device__ __nv_bfloat16 g_akh[B_*S_*D_], g_akl[B_*S_*D_];
__device__ __nv_bfloat16 g_avh[B_*S_*D_], g_avl[B_*S_*D_];
__device__ __nv_bfloat16 g_wqh[D_*D_], g_wql[D_*D_];
__device__ __nv_bfloat16 g_wkh[D_*D_], g_wkl[D_*D_];
__device__ __nv_bfloat16 g_wvh[D_*D_], g_wvl[D_*D_];
__device__ __nv_bfloat16 g_woh[D_*D_], g_wol[D_*D_];

// ===========================================================================
// Helpers
// ===========================================================================
__device__ __forceinline__ uint32_t smem_u32(const void* p) {
    uint32_t a;
    asm("{ .reg .u64 t; cvta.to.shared.u64 t, %1; cvt.u32.u64 %0, t; }"
        : "=r"(a) : "l"(p));
    return a;
}
__device__ __forceinline__ void cp16(uint32_t dst, const void* src) {
    asm volatile("cp.async.cg.shared.global [%0], [%1], 16;" :: "r"(dst), "l"(src));
}
__device__ __forceinline__ void cp4(uint32_t dst, const void* src) {
    asm volatile("cp.async.ca.shared.global [%0], [%1], 4;" :: "r"(dst), "l"(src));
}
__device__ __forceinline__ void ldmx4(uint32_t& r0, uint32_t& r1,
                                      uint32_t& r2, uint32_t& r3, uint32_t addr) {
    asm volatile("ldmatrix.sync.aligned.m8n8.x4.shared.b16 {%0,%1,%2,%3}, [%4];"
                 : "=r"(r0), "=r"(r1), "=r"(r2), "=r"(r3) : "r"(addr));
}
__device__ __forceinline__ void ldmx4t(uint32_t& r0, uint32_t& r1,
                                       uint32_t& r2, uint32_t& r3, uint32_t addr) {
    asm volatile("ldmatrix.sync.aligned.m8n8.x4.trans.shared.b16 {%0,%1,%2,%3}, [%4];"
                 : "=r"(r0), "=r"(r1), "=r"(r2), "=r"(r3) : "r"(addr));
}
__device__ __forceinline__ void mma16816(float* c, const uint32_t* a,
                                         uint32_t b0, uint32_t b1) {
    asm volatile(
        "mma.sync.aligned.m16n8k16.row.col.f32.bf16.bf16.f32 "
        "{%0,%1,%2,%3}, {%4,%5,%6,%7}, {%8,%9}, {%0,%1,%2,%3};"
        : "+f"(c[0]), "+f"(c[1]), "+f"(c[2]), "+f"(c[3])
        : "r"(a[0]), "r"(a[1]), "r"(a[2]), "r"(a[3]), "r"(b0), "r"(b1));
}
__device__ __forceinline__ uint32_t pack2(unsigned short a, unsigned short b) {
    return (uint32_t)a | ((uint32_t)b << 16);
}
__device__ __forceinline__ uint32_t cvt2bf(float hi_elem, float lo_elem) {
    uint32_t r;
    asm("cvt.rn.bf16x2.f32 %0, %1, %2;" : "=r"(r) : "f"(hi_elem), "f"(lo_elem));
    return r;
}
__device__ __forceinline__ float bflo(uint32_t p) { return __uint_as_float(p << 16); }
__device__ __forceinline__ float bfhi(uint32_t p) { return __uint_as_float(p & 0xFFFF0000u); }

// ===========================================================================
// Split kernels (batched)
// ===========================================================================
__device__ __forceinline__ void split_one(const float* x, __nv_bfloat16* hi,
                                          __nv_bfloat16* lo, int i) {
    float4 v = ((const float4*)x)[i];
    float f[4] = {v.x, v.y, v.z, v.w};
    unsigned short h[4], l[4];
    #pragma unroll
    for (int j = 0; j < 4; j++) {
        __nv_bfloat16 bh = __float2bfloat16(f[j]);
        float r = f[j] - __bfloat162float(bh);
        h[j] = __bfloat16_as_ushort(bh);
        l[j] = __bfloat16_as_ushort(__float2bfloat16(r));
    }
    ((uint2*)hi)[i] = make_uint2(pack2(h[0], h[1]), pack2(h[2], h[3]));
    ((uint2*)lo)[i] = make_uint2(pack2(l[0], l[1]), pack2(l[2], l[3]));
}

__global__ __launch_bounds__(256) void split_acts(
    const float* __restrict__ q, const float* __restrict__ k, const float* __restrict__ v,
    __nv_bfloat16* qh, __nv_bfloat16* ql, __nv_bfloat16* kh, __nv_bfloat16* kl,
    __nv_bfloat16* vh, __nv_bfloat16* vl)
{
    int i = blockIdx.x * 256 + threadIdx.x;
    int z = blockIdx.y;
    const float* x = (z == 0) ? q : (z == 1) ? k : v;
    __nv_bfloat16* hi = (z == 0) ? qh : (z == 1) ? kh : vh;
    __nv_bfloat16* lo = (z == 0) ? ql : (z == 1) ? kl : vl;
    split_one(x, hi, lo, i);
}

__global__ __launch_bounds__(256) void split_weights(
    const float* __restrict__ w0, const float* __restrict__ w1,
    const float* __restrict__ w2, const float* __restrict__ w3,
    __nv_bfloat16* h0, __nv_bfloat16* l0, __nv_bfloat16* h1, __nv_bfloat16* l1,
    __nv_bfloat16* h2, __nv_bfloat16* l2, __nv_bfloat16* h3, __nv_bfloat16* l3)
{
    int i = blockIdx.x * 256 + threadIdx.x;
    int z = blockIdx.y;
    const float* x = (z == 0) ? w0 : (z == 1) ? w1 : (z == 2) ? w2 : w3;
    __nv_bfloat16* hi = (z == 0) ? h0 : (z == 1) ? h1 : (z == 2) ? h2 : h3;
    __nv_bfloat16* lo = (z == 0) ? l0 : (z == 1) ? l1 : (z == 2) ? l2 : l3;
    split_one(x, hi, lo, i);
}

// ===========================================================================
// GEMM (NT + bias): 128x128 tile, 256 threads, 2-stage, 2 CTAs/SM, z-batched.
// ===========================================================================
template<bool SPLIT>
__global__ __launch_bounds__(256, 2) void gemm3(
    const __nv_bfloat16* __restrict__ a0h, const __nv_bfloat16* __restrict__ a0l,
    const __nv_bfloat16* __restrict__ w0h, const __nv_bfloat16* __restrict__ w0l,
    const float* __restrict__ bias0,
    const __nv_bfloat16* __restrict__ a1h, const __nv_bfloat16* __restrict__ a1l,
    const __nv_bfloat16* __restrict__ w1h, const __nv_bfloat16* __restrict__ w1l,
    const float* __restrict__ bias1,
    const __nv_bfloat16* __restrict__ a2h, const __nv_bfloat16* __restrict__ a2l,
    const __nv_bfloat16* __restrict__ w2h, const __nv_bfloat16* __restrict__ w2l,
    const float* __restrict__ bias2,
    float* __restrict__ Cf,
    __nv_bfloat16* __restrict__ C0h, __nv_bfloat16* __restrict__ C0l,
    __nv_bfloat16* __restrict__ C1h, __nv_bfloat16* __restrict__ C1l,
    __nv_bfloat16* __restrict__ C2h, __nv_bfloat16* __restrict__ C2l)
{
    extern __shared__ char dynsm[];
    const uint32_t smb = smem_u32(dynsm);
    const int tid = threadIdx.x;
    const int l = tid & 31;
    const int wid = tid >> 5;
    const int wm = (wid & 3) * 32;
    const int wn = (wid >> 2) * 64;
    const int bm = blockIdx.y * BM;
    const int bn = blockIdx.x * BN;
    const int z = blockIdx.z;

    const __nv_bfloat16* aH = (z == 0) ? a0h : (z == 1) ? a1h : a2h;
    const __nv_bfloat16* aL = (z == 0) ? a0l : (z == 1) ? a1l : a2l;
    const __nv_bfloat16* bH = (z == 0) ? w0h : (z == 1) ? w1h : w2h;
    const __nv_bfloat16* bL = (z == 0) ? w0l : (z == 1) ? w1l : w2l;
    const float* bias = (z == 0) ? bias0 : (z == 1) ? bias1 : bias2;
    __nv_bfloat16* Chi = (z == 0) ? C0h : (z == 1) ? C1h : C2h;
    __nv_bfloat16* Clo = (z == 0) ? C0l : (z == 1) ? C1l : C2l;

    float acc[2][8][4];
    #pragma unroll
    for (int mi = 0; mi < 2; mi++)
        #pragma unroll
        for (int nj = 0; nj < 8; nj++)
            #pragma unroll
            for (int q = 0; q < 4; q++) acc[mi][nj][q] = 0.0f;

    auto issue = [&](int c, int buf) {
        const int kk = c * BK;
        const uint32_t base = smb + buf * BUF;
        #pragma unroll
        for (int i = 0; i < 2; i++) {
            int idx = tid + i * 256;
            int row = idx >> 2, s4 = (idx & 3) * 8;
            uint32_t off = (uint32_t)(row * 40 + s4) * 2;
            cp16(base + off,                   aH + (size_t)(bm + row) * KDIM + kk + s4);
            cp16(base + A_T + off,             aL + (size_t)(bm + row) * KDIM + kk + s4);
            cp16(base + 2 * A_T + off,         bH + (size_t)(bn + row) * KDIM + kk + s4);
            cp16(base + 2 * A_T + B_T + off,   bL + (size_t)(bn + row) * KDIM + kk + s4);
        }
        asm volatile("cp.async.commit_group;" ::: "memory");
    };

    auto compute = [&](int buf) {
        const uint32_t aBh = smb + buf * BUF;
        const uint32_t aBl = aBh + A_T;
        const uint32_t bBh = aBh + 2 * A_T;
        const uint32_t bBl = bBh + B_T;
        const int bmat = l >> 3, br8 = l & 7;
        #pragma unroll
        for (int ks = 0; ks < 2; ks++) {
            uint32_t ah[2][4], al[2][4];
            #pragma unroll
            for (int mi = 0; mi < 2; mi++) {
                uint32_t aoff = (uint32_t)((wm + mi * 16 + (l & 15)) * 40
                                           + ks * 16 + (l >> 4) * 8) * 2;
                ldmx4(ah[mi][0], ah[mi][1], ah[mi][2], ah[mi][3], aBh + aoff);
                ldmx4(al[mi][0], al[mi][1], al[mi][2], al[mi][3], aBl + aoff);
            }
            #pragma unroll
            for (int p = 0; p < 4; p++) {
                uint32_t boff = (uint32_t)((wn + p * 16 + ((bmat >> 1) << 3) + br8) * 40
                                           + ks * 16 + ((bmat & 1) << 3)) * 2;
                uint32_t bh0, bh1, bh2, bh3, bl0, bl1, bl2, bl3;
                ldmx4(bh0, bh1, bh2, bh3, bBh + boff);
                ldmx4(bl0, bl1, bl2, bl3, bBl + boff);
                #pragma unroll
                for (int mi = 0; mi < 2; mi++) {
                    mma16816(acc[mi][2 * p],     ah[mi], bh0, bh1);
                    mma16816(acc[mi][2 * p + 1], ah[mi], bh2, bh3);
                    mma16816(acc[mi][2 * p],     ah[mi], bl0, bl1);
                    mma16816(acc[mi][2 * p + 1], ah[mi], bl2, bl3);
                    mma16816(acc[mi][2 * p],     al[mi], bh0, bh1);
                    mma16816(acc[mi][2 * p + 1], al[mi], bh2, bh3);
                }
            }
        }
    };

    issue(0, 0);
    for (int c = 0; c < CHUNKS; ++c) {
        if (c + 1 < CHUNKS) {
            issue(c + 1, (c + 1) & 1);
            asm volatile("cp.async.wait_group 1;" ::: "memory");
        } else {
            asm volatile("cp.async.wait_group 0;" ::: "memory");
        }
        __syncthreads();
        compute(c & 1);
        __syncthreads();
    }

    #pragma unroll
    for (int mi = 0; mi < 2; mi++) {
        int r0 = bm + wm + mi * 16 + (l >> 2);
        #pragma unroll
        for (int nj = 0; nj < 8; nj++) {
            int col = bn + wn + nj * 8 + (l & 3) * 2;
            float2 bv = *(const float2*)&bias[col];
            float v0 = acc[mi][nj][0] + bv.x;
            float v1 = acc[mi][nj][1] + bv.y;
            float v2 = acc[mi][nj][2] + bv.x;
            float v3 = acc[mi][nj][3] + bv.y;
            if (SPLIT) {
                uint32_t ph = cvt2bf(v1, v0);
                uint32_t pl = cvt2bf(v1 - bfhi(ph), v0 - bflo(ph));
                *(uint32_t*)&Chi[(size_t)r0 * D_ + col] = ph;
                *(uint32_t*)&Clo[(size_t)r0 * D_ + col] = pl;
                ph = cvt2bf(v3, v2);
                pl = cvt2bf(v3 - bfhi(ph), v2 - bflo(ph));
                *(uint32_t*)&Chi[(size_t)(r0 + 8) * D_ + col] = ph;
                *(uint32_t*)&Clo[(size_t)(r0 + 8) * D_ + col] = pl;
            } else {
                *(float2*)&Cf[(size_t)r0 * D_ + col] = make_float2(v0, v1);
                *(float2*)&Cf[(size_t)(r0 + 8) * D_ + col] = make_float2(v2, v3);
            }
        }
    }
}

// ===========================================================================
// Tensor-core flash attention (bf16 hi/lo, fp32 softmax). 64-key tiles.
// ===========================================================================
__global__ __launch_bounds__(256, 2) void attn_mma(
    const __nv_bfloat16* __restrict__ qHi, const __nv_bfloat16* __restrict__ qLo,
    const __nv_bfloat16* __restrict__ kHi, const __nv_bfloat16* __restrict__ kLo,
    const __nv_bfloat16* __restrict__ vHi, const __nv_bfloat16* __restrict__ vLo,
    const int* __restrict__ mask,
    __nv_bfloat16* __restrict__ cHi, __nv_bfloat16* __restrict__ cLo)
{
    extern __shared__ char dynsm[];
    const uint32_t smb = smem_u32(dynsm);
    const int tid = threadIdx.x;
    const int w = tid >> 5, l = tid & 31;
    const int b = blockIdx.z, h = blockIdx.y;
    const int q0 = blockIdx.x * 128;
    const size_t bS = (size_t)b * S_;
    const int hd = h * DK_;

    auto load_q = [&](const __nv_bfloat16* g, uint32_t off) {
        #pragma unroll
        for (int t = 0; t < 4; t++) {
            int idx = tid + t * 256;
            int row = idx >> 3, seg = (idx & 7) * 8;
            cp16(smb + off + (uint32_t)(row * SK + seg) * 2,
                 g + (bS + q0 + row) * D_ + hd + seg);
        }
    };
    auto load_kv_tile = [&](const __nv_bfloat16* g, uint32_t off, int tok0) {
        #pragma unroll
        for (int t = 0; t < 2; t++) {
            int idx = tid + t * 256;
            int row = idx >> 3, seg = (idx & 7) * 8;
            cp16(smb + off + (uint32_t)(row * SK + seg) * 2,
                 g + (bS + tok0 + row) * D_ + hd + seg);
        }
    };
    auto load_kv = [&](int kt, int buf) {
        int tok0 = kt * 64;
        load_kv_tile(kHi, KV_OFF(buf, 0), tok0);
        load_kv_tile(kLo, KV_OFF(buf, 1), tok0);
        load_kv_tile(vHi, KV_OFF(buf, 2), tok0);
        load_kv_tile(vLo, KV_OFF(buf, 3), tok0);
        if (tid < 64) cp4(smb + MS_OFF + (uint32_t)(buf * 64 + tid) * 4,
                          mask + b * S_ + tok0 + tid);
    };

    load_q(qHi, QH_OFF);
    load_q(qLo, QL_OFF);
    load_kv(0, 0);
    asm volatile("cp.async.commit_group;" ::: "memory");

    float Oacc[8][4];
    #pragma unroll
    for (int nf = 0; nf < 8; nf++)
        #pragma unroll
        for (int q = 0; q < 4; q++) Oacc[nf][q] = 0.0f;
    float mrun0 = -1e30f, mrun1 = -1e30f, lrun0 = 0.0f, lrun1 = 0.0f;

    const uint32_t a_off = (uint32_t)((w * 16 + (l & 15)) * SK + ((l >> 4) << 3)) * 2;
    const int bmat = l >> 3, br8 = l & 7;

    for (int kt = 0; kt < 32; kt++) {
        const int buf = kt & 1;
        if (kt < 31) {
            load_kv(kt + 1, buf ^ 1);
            asm volatile("cp.async.commit_group;" ::: "memory");
            asm volatile("cp.async.wait_group 1;" ::: "memory");
        } else {
            asm volatile("cp.async.wait_group 0;" ::: "memory");
        }
        __syncthreads();

        const uint32_t KhB = smb + KV_OFF(buf, 0), KlB = smb + KV_OFF(buf, 1);
        const uint32_t VhB = smb + KV_OFF(buf, 2), VlB = smb + KV_OFF(buf, 3);
        const int* ms = (const int*)(dynsm + MS_OFF + buf * 256);

        float sacc[8][4];
        #pragma unroll
        for (int f = 0; f < 8; f++)
            #pragma unroll
            for (int q = 0; q < 4; q++) sacc[f][q] = 0.0f;

        #pragma unroll
        for (int kc = 0; kc < 4; kc++) {
            uint32_t aH[4], aL[4];
            ldmx4(aH[0], aH[1], aH[2], aH[3], smb + QH_OFF + a_off + kc * 32);
            ldmx4(aL[0], aL[1], aL[2], aL[3], smb + QL_OFF + a_off + kc * 32);
            #pragma unroll
            for (int np = 0; np < 4; np++) {
                uint32_t badr = (uint32_t)((np * 16 + ((bmat >> 1) << 3) + br8) * SK
                                           + kc * 16 + ((bmat & 1) << 3)) * 2;
                uint32_t bh0, bh1, bh2, bh3, bl0, bl1, bl2, bl3;
                ldmx4(bh0, bh1, bh2, bh3, KhB + badr);
                ldmx4(bl0, bl1, bl2, bl3, KlB + badr);
                mma16816(sacc[2 * np],     aH, bh0, bh1);
                mma16816(sacc[2 * np + 1], aH, bh2, bh3);
                mma16816(sacc[2 * np],     aH, bl0, bl1);
                mma16816(sacc[2 * np + 1], aH, bl2, bl3);
                mma16816(sacc[2 * np],     aL, bh0, bh1);
                mma16816(sacc[2 * np + 1], aL, bh2, bh3);
            }
        }

        float mx0 = -1e30f, mx1 = -1e30f;
        #pragma unroll
        for (int f = 0; f < 8; f++) {
            int c0 = f * 8 + (l & 3) * 2;
            int mk0 = ms[c0], mk1 = ms[c0 + 1];
            float t0 = mk0 ? sacc[f][0] * 0.125f : -1e30f;
            float t1 = mk1 ? sacc[f][1] * 0.125f : -1e30f;
            float t2 = mk0 ? sacc[f][2] * 0.125f : -1e30f;
            float t3 = mk1 ? sacc[f][3] * 0.125f : -1e30f;
            sacc[f][0] = t0; sacc[f][1] = t1; sacc[f][2] = t2; sacc[f][3] = t3;
            mx0 = fmaxf(mx0, fmaxf(t0, t1));
            mx1 = fmaxf(mx1, fmaxf(t2, t3));
        }
        mx0 = fmaxf(mx0, __shfl_xor_sync(0xffffffffu, mx0, 1));
        mx0 = fmaxf(mx0, __shfl_xor_sync(0xffffffffu, mx0, 2));
        mx1 = fmaxf(mx1, __shfl_xor_sync(0xffffffffu, mx1, 1));
        mx1 = fmaxf(mx1, __shfl_xor_sync(0xffffffffu, mx1, 2));
        float mn0 = fmaxf(mrun0, mx0), mn1 = fmaxf(mrun1, mx1);
        float cor0 = __expf(mrun0 - mn0), cor1 = __expf(mrun1 - mn1);
        mrun0 = mn0; mrun1 = mn1;
        float sum0 = 0.0f, sum1 = 0.0f;
        #pragma unroll
        for (int f = 0; f < 8; f++) {
            float p0 = __expf(sacc[f][0] - mn0);
            float p1 = __expf(sacc[f][1] - mn0);
            float p2 = __expf(sacc[f][2] - mn1);
            float p3 = __expf(sacc[f][3] - mn1);
            sacc[f][0] = p0; sacc[f][1] = p1; sacc[f][2] = p2; sacc[f][3] = p3;
            sum0 += p0 + p1; sum1 += p2 + p3;
        }
        sum0 += __shfl_xor_sync(0xffffffffu, sum0, 1);
        sum0 += __shfl_xor_sync(0xffffffffu, sum0, 2);
        sum1 += __shfl_xor_sync(0xffffffffu, sum1, 1);
        sum1 += __shfl_xor_sync(0xffffffffu, sum1, 2);
        lrun0 = lrun0 * cor0 + sum0;
        lrun1 = lrun1 * cor1 + sum1;
        #pragma unroll
        for (int nf = 0; nf < 8; nf++) {
            Oacc[nf][0] *= cor0; Oacc[nf][1] *= cor0;
            Oacc[nf][2] *= cor1; Oacc[nf][3] *= cor1;
        }

        #pragma unroll
        for (int kc2 = 0; kc2 < 4; kc2++) {
            const float* f0 = sacc[2 * kc2];
            const float* f1 = sacc[2 * kc2 + 1];
            uint32_t aH2[4], aL2[4];
            aH2[0] = cvt2bf(f0[1], f0[0]);
            aH2[1] = cvt2bf(f0[3], f0[2]);
            aH2[2] = cvt2bf(f1[1], f1[0]);
            aH2[3] = cvt2bf(f1[3], f1[2]);
            aL2[0] = cvt2bf(f0[1] - bfhi(aH2[0]), f0[0] - bflo(aH2[0]));
            aL2[1] = cvt2bf(f0[3] - bfhi(aH2[1]), f0[2] - bflo(aH2[1]));
            aL2[2] = cvt2bf(f1[1] - bfhi(aH2[2]), f1[0] - bflo(aH2[2]));
            aL2[3] = cvt2bf(f1[3] - bfhi(aH2[3]), f1[2] - bflo(aH2[3]));
            #pragma unroll
            for (int nf = 0; nf < 4; nf++) {
                uint32_t vadr = (uint32_t)((kc2 * 16 + (l & 15)) * SK
                                           + nf * 16 + ((l >> 4) << 3)) * 2;
                uint32_t vh0, vh1, vh2, vh3, vl0, vl1, vl2, vl3;
                ldmx4t(vh0, vh1, vh2, vh3, VhB + vadr);
                ldmx4t(vl0, vl1, vl2, vl3, VlB + vadr);
                mma16816(Oacc[2 * nf],     aH2, vh0, vh1);
                mma16816(Oacc[2 * nf + 1], aH2, vh2, vh3);
                mma16816(Oacc[2 * nf],     aH2, vl0, vl1);
                mma16816(Oacc[2 * nf + 1], aH2, vl2, vl3);
                mma16816(Oacc[2 * nf],     aL2, vh0, vh1);
                mma16816(Oacc[2 * nf + 1], aL2, vh2, vh3);
            }
        }
        __syncthreads();
    }

    const float inv0 = 1.0f / lrun0;
    const float inv1 = 1.0f / lrun1;
    const int r0 = q0 + w * 16 + (l >> 2);
    #pragma unroll
    for (int nf = 0; nf < 8; nf++) {
        int col = hd + nf * 8 + (l & 3) * 2;
        float v0 = Oacc[nf][0] * inv0, v1 = Oacc[nf][1] * inv0;
        uint32_t ph = cvt2bf(v1, v0);
        uint32_t pl = cvt2bf(v1 - bfhi(ph), v0 - bflo(ph));
        *(uint32_t*)&cHi[(bS + r0) * D_ + col] = ph;
        *(uint32_t*)&cLo[(bS + r0) * D_ + col] = pl;
        float v2 = Oacc[nf][2] * inv1, v3 = Oacc[nf][3] * inv1;
        ph = cvt2bf(v3, v2);
        pl = cvt2bf(v3 - bfhi(ph), v2 - bflo(ph));
        *(uint32_t*)&cHi[(bS + r0 + 8) * D_ + col] = ph;
        *(uint32_t*)&cLo[(bS + r0 + 8) * D_ + col] = pl;
    }
}

// ---------------------------------------------------------------------------
extern "C" void kernel_launch(void* const* d_in, const int* in_sizes, int n_in,
                              void* d_out, int out_size)
{
    (void)in_sizes; (void)n_in; (void)out_size;
    const float* query = (const float*)d_in[0];
    const float* key   = (const float*)d_in[1];
    const float* value = (const float*)d_in[2];
    const int*   mask  = (const int*)d_in[3];
    const float* Wq = (const float*)d_in[4];
    const float* bq = (const float*)d_in[5];
    const float* Wk = (const float*)d_in[6];
    const float* bk = (const float*)d_in[7];
    const float* Wv = (const float*)d_in[8];
    const float* bv = (const float*)d_in[9];
    const float* Wo = (const float*)d_in[10];
    const float* bo = (const float*)d_in[11];
    float* out = (float*)d_out;

    __nv_bfloat16 *qh, *ql, *kh, *kl, *vh, *vl, *ch, *cl;
    __nv_bfloat16 *aqh, *aql, *akh, *akl, *avh, *avl;
    __nv_bfloat16 *wqh, *wql, *wkh, *wkl, *wvh, *wvl, *woh, *wol;
    cudaGetSymbolAddress((void**)&qh, g_qh);   cudaGetSymbolAddress((void**)&ql, g_ql);
    cudaGetSymbolAddress((void**)&kh, g_kh);   cudaGetSymbolAddress((void**)&kl, g_kl);
    cudaGetSymbolAddress((void**)&vh, g_vh);   cudaGetSymbolAddress((void**)&vl, g_vl);
    cudaGetSymbolAddress((void**)&ch, g_ch);   cudaGetSymbolAddress((void**)&cl, g_cl);
    cudaGetSymbolAddress((void**)&aqh, g_aqh); cudaGetSymbolAddress((void**)&aql, g_aql);
    cudaGetSymbolAddress((void**)&akh, g_akh); cudaGetSymbolAddress((void**)&akl, g_akl);
    cudaGetSymbolAddress((void**)&avh, g_avh); cudaGetSymbolAddress((void**)&avl, g_avl);
    cudaGetSymbolAddress((void**)&wqh, g_wqh); cudaGetSymbolAddress((void**)&wql, g_wql);
    cudaGetSymbolAddress((void**)&wkh, g_wkh); cudaGetSymbolAddress((void**)&wkl, g_wkl);
    cudaGetSymbolAddress((void**)&wvh, g_wvh); cudaGetSymbolAddress((void**)&wvl, g_wvl);
    cudaGetSymbolAddress((void**)&woh, g_woh); cudaGetSymbolAddress((void**)&wol, g_wol);

    const int actN4 = B_ * S_ * D_ / 4;   // 1048576
    const int wN4   = D_ * D_ / 4;        // 262144

    cudaFuncSetAttribute(gemm3<true>, cudaFuncAttributeMaxDynamicSharedMemorySize,
                         GEMM_SMEM);
    cudaFuncSetAttribute(gemm3<false>, cudaFuncAttributeMaxDynamicSharedMemorySize,
                         GEMM_SMEM);
    cudaFuncSetAttribute(attn_mma, cudaFuncAttributeMaxDynamicSharedMemorySize,
                         ATTN_SMEM);

    // Splits (2 batched launches)
    split_acts<<<dim3(actN4 / 256, 3), 256>>>(query, key, value,
                                              aqh, aql, akh, akl, avh, avl);
    split_weights<<<dim3(wN4 / 256, 4), 256>>>(Wq, Wk, Wv, Wo,
                                               wqh, wql, wkh, wkl,
                                               wvh, wvl, woh, wol);

    // Fused Q/K/V projections (one launch, grid.z = 3)
    dim3 ggrid(D_ / BN, (B_ * S_) / BM, 3);   // (8, 32, 3)
    gemm3<true><<<ggrid, 256, GEMM_SMEM>>>(
        aqh, aql, wqh, wql, bq,
        akh, akl, wkh, wkl, bk,
        avh, avl, wvh, wvl, bv,
        nullptr, qh, ql, kh, kl, vh, vl);

    // Attention
    dim3 agrid(S_ / 128, H_, B_);
    attn_mma<<<agrid, 256, ATTN_SMEM>>>(qh, ql, kh, kl, vh, vl, mask, ch, cl);

    // Output projection (fp32 out)
    dim3 ogrid(D_ / BN, (B_ * S_) / BM, 1);   // (8, 32, 1)
    gemm3<false><<<ogrid, 256, GEMM_SMEM>>>(
        ch, cl, woh, wol, bo,
        ch, cl, woh, wol, bo,
        ch, cl, woh, wol, bo,
        out, nullptr, nullptr, nullptr, nullptr, nullptr, nullptr);
}